// round 12
// baseline (speedup 1.0000x reference)
#include <cuda_runtime.h>
#include <cuda_bf16.h>
#include <cstdint>

// Problem constants
#define SEQL   1024
#define DMODEL 1024
#define NBATCH 4
#define NHEADS 16
#define DEPTH  64
#define NHTOT  (NBATCH * NHEADS)   // 64
#define NLROWS (NBATCH * SEQL)     // 4096
#define QROWS  (NHTOT * SEQL)      // 65536

// ---------------------------------------------------------------------------
// Scratch (device globals; allocation-free per harness rules)
// ---------------------------------------------------------------------------
__device__ __align__(128) unsigned short g_QE[(size_t)QROWS * SEQL]; // bf16 diag-shifted band
__device__ float g_zbias[DMODEL];                                   // zero-initialized
// bf16 hi/lo split buffers
__device__ __align__(128) unsigned short g_Xhi[3][NLROWS * DMODEL]; // q/k/v ins; [0] reused for AO
__device__ __align__(128) unsigned short g_Xlo[3][NLROWS * DMODEL];
__device__ __align__(128) unsigned short g_Bhi[4][DMODEL * DMODEL]; // Wq/Wk/Wv/Wo ^T
__device__ __align__(128) unsigned short g_Blo[4][DMODEL * DMODEL];
__device__ __align__(128) unsigned short g_Ehi[SEQL * DEPTH];
__device__ __align__(128) unsigned short g_Elo[SEQL * DEPTH];
__device__ __align__(128) unsigned short g_Qhi[QROWS * DEPTH];
__device__ __align__(128) unsigned short g_Qlo[QROWS * DEPTH];
__device__ __align__(128) unsigned short g_Khi[QROWS * DEPTH];
__device__ __align__(128) unsigned short g_Klo[QROWS * DEPTH];
__device__ __align__(128) unsigned short g_Vhi[QROWS * DEPTH];
__device__ __align__(128) unsigned short g_Vlo[QROWS * DEPTH];
__device__ __align__(128) unsigned short g_Vthi[QROWS * DEPTH]; // [nh][64 d][1024 key]
__device__ __align__(128) unsigned short g_Vtlo[QROWS * DEPTH];

// ---------------------------------------------------------------------------
// Helpers
// ---------------------------------------------------------------------------
__device__ __forceinline__ uint32_t smem_u32(const void* p) {
    uint32_t a;
    asm("{ .reg .u64 t; cvta.to.shared.u64 t, %1; cvt.u32.u64 %0, t; }"
        : "=r"(a) : "l"(p));
    return a;
}
__device__ __forceinline__ uint32_t packbf(float a, float b) {
    __nv_bfloat162 t = __floats2bfloat162_rn(a, b);   // x=a (low), y=b (high)
    return *reinterpret_cast<uint32_t*>(&t);
}
__device__ __forceinline__ void ldsm4(uint32_t addr, uint32_t& r0, uint32_t& r1,
                                      uint32_t& r2, uint32_t& r3) {
    asm volatile("ldmatrix.sync.aligned.m8n8.x4.shared.b16 {%0,%1,%2,%3}, [%4];"
                 : "=r"(r0), "=r"(r1), "=r"(r2), "=r"(r3) : "r"(addr));
}
__device__ __forceinline__ void cp16(uint32_t saddr, const void* g) {
    asm volatile("cp.async.cg.shared.global [%0], [%1], 16;"
                 :: "r"(saddr), "l"(g) : "memory");
}
__device__ __forceinline__ void cp_commit() {
    asm volatile("cp.async.commit_group;" ::: "memory");
}
template <int N>
__device__ __forceinline__ void cp_wait() {
    asm volatile("cp.async.wait_group %0;" :: "n"(N) : "memory");
}
#define MMA_BF16(c, a, b) \
    asm volatile("mma.sync.aligned.m16n8k16.row.col.f32.bf16.bf16.f32 " \
                 "{%0,%1,%2,%3}, {%4,%5,%6,%7}, {%8,%9}, {%0,%1,%2,%3};" \
                 : "+f"((c)[0]), "+f"((c)[1]), "+f"((c)[2]), "+f"((c)[3]) \
                 : "r"((a)[0]), "r"((a)[1]), "r"((a)[2]), "r"((a)[3]), \
                   "r"((b)[0]), "r"((b)[1]))

// ---------------------------------------------------------------------------
// Conversion kernels (fused multi-tensor variants)
// ---------------------------------------------------------------------------
__global__ __launch_bounds__(256) void ra_conv_hilo3(
    const float* __restrict__ x0, const float* __restrict__ x1,
    const float* __restrict__ x2,
    unsigned short* __restrict__ h0, unsigned short* __restrict__ l0,
    unsigned short* __restrict__ h1, unsigned short* __restrict__ l1,
    unsigned short* __restrict__ h2, unsigned short* __restrict__ l2, int n4)
{
    const int z = blockIdx.y;
    const float* x = z == 0 ? x0 : (z == 1 ? x1 : x2);
    unsigned short* hi = z == 0 ? h0 : (z == 1 ? h1 : h2);
    unsigned short* lo = z == 0 ? l0 : (z == 1 ? l1 : l2);
    int i = blockIdx.x * 256 + threadIdx.x;
    if (i >= n4) return;
    float4 v = ((const float4*)x)[i];
    uint32_t hp0 = packbf(v.x, v.y);
    uint32_t hp1 = packbf(v.z, v.w);
    uint32_t lp0 = packbf(v.x - __uint_as_float(hp0 << 16),
                          v.y - __uint_as_float(hp0 & 0xffff0000u));
    uint32_t lp1 = packbf(v.z - __uint_as_float(hp1 << 16),
                          v.w - __uint_as_float(hp1 & 0xffff0000u));
    ((uint2*)hi)[i] = make_uint2(hp0, hp1);
    ((uint2*)lo)[i] = make_uint2(lp0, lp1);
}

__global__ __launch_bounds__(256) void ra_conv_hilo(
    const float* __restrict__ x, unsigned short* __restrict__ hi,
    unsigned short* __restrict__ lo, int n4)
{
    int i = blockIdx.x * 256 + threadIdx.x;
    if (i >= n4) return;
    float4 v = ((const float4*)x)[i];
    uint32_t hp0 = packbf(v.x, v.y);
    uint32_t hp1 = packbf(v.z, v.w);
    uint32_t lp0 = packbf(v.x - __uint_as_float(hp0 << 16),
                          v.y - __uint_as_float(hp0 & 0xffff0000u));
    uint32_t lp1 = packbf(v.z - __uint_as_float(hp1 << 16),
                          v.w - __uint_as_float(hp1 & 0xffff0000u));
    ((uint2*)hi)[i] = make_uint2(hp0, hp1);
    ((uint2*)lo)[i] = make_uint2(lp0, lp1);
}

// W [K=1024, N=1024] -> W^T hi/lo bf16 [N, K]; 4 weights fused via blockIdx.z
__global__ __launch_bounds__(256) void ra_conv_wt4(
    const float* __restrict__ W0, const float* __restrict__ W1,
    const float* __restrict__ W2, const float* __restrict__ W3,
    unsigned short* __restrict__ h0, unsigned short* __restrict__ l0,
    unsigned short* __restrict__ h1, unsigned short* __restrict__ l1,
    unsigned short* __restrict__ h2, unsigned short* __restrict__ l2,
    unsigned short* __restrict__ h3, unsigned short* __restrict__ l3)
{
    const int z = blockIdx.z;
    const float* W = z == 0 ? W0 : (z == 1 ? W1 : (z == 2 ? W2 : W3));
    unsigned short* hiT = z == 0 ? h0 : (z == 1 ? h1 : (z == 2 ? h2 : h3));
    unsigned short* loT = z == 0 ? l0 : (z == 1 ? l1 : (z == 2 ? l2 : l3));
    __shared__ float tile[32][33];
    const int nx = blockIdx.x * 32 + threadIdx.x;
    const int k0 = blockIdx.y * 32;
    #pragma unroll
    for (int r = 0; r < 4; r++)
        tile[threadIdx.y + r * 8][threadIdx.x] =
            W[(size_t)(k0 + threadIdx.y + r * 8) * DMODEL + nx];
    __syncthreads();
    const int kx = k0 + threadIdx.x;
    const int n0 = blockIdx.x * 32;
    #pragma unroll
    for (int r = 0; r < 4; r++) {
        float v = tile[threadIdx.x][threadIdx.y + r * 8];
        __nv_bfloat16 hb = __float2bfloat16(v);
        __nv_bfloat16 lb = __float2bfloat16(v - __bfloat162float(hb));
        size_t o = (size_t)(n0 + threadIdx.y + r * 8) * DMODEL + kx;
        hiT[o] = __bfloat16_as_ushort(hb);
        loT[o] = __bfloat16_as_ushort(lb);
    }
}

// V [nh][1024 key][64 d] hi/lo -> Vt [nh][64 d][1024 key] hi/lo
__global__ __launch_bounds__(128) void ra_vt(
    const unsigned short* __restrict__ Vhi, const unsigned short* __restrict__ Vlo,
    unsigned short* __restrict__ Vthi, unsigned short* __restrict__ Vtlo)
{
    __shared__ unsigned short th[64 * 72];
    __shared__ unsigned short tl[64 * 72];
    const int head = blockIdx.y, kt = blockIdx.x;
    const int t = threadIdx.x, lr = t >> 1, lc = (t & 1) * 32;
    {
        const uint4* sh = (const uint4*)(Vhi + ((size_t)(head * SEQL + kt * 64 + lr)) * 64 + lc);
        const uint4* sl = (const uint4*)(Vlo + ((size_t)(head * SEQL + kt * 64 + lr)) * 64 + lc);
        uint4* dh = (uint4*)(th + lr * 72 + lc);
        uint4* dl = (uint4*)(tl + lr * 72 + lc);
        #pragma unroll
        for (int u = 0; u < 4; u++) { dh[u] = sh[u]; dl[u] = sl[u]; }
    }
    __syncthreads();
    unsigned short* oh = Vthi + ((size_t)(head * 64 + lr)) * SEQL + kt * 64 + lc;
    unsigned short* ol = Vtlo + ((size_t)(head * 64 + lr)) * SEQL + kt * 64 + lc;
    #pragma unroll
    for (int v = 0; v < 4; v++) {
        uint32_t wh[4], wl[4];
        #pragma unroll
        for (int u = 0; u < 4; u++) {
            const int k = lc + v * 8 + u * 2;
            wh[u] = (uint32_t)th[k * 72 + lr] | ((uint32_t)th[(k + 1) * 72 + lr] << 16);
            wl[u] = (uint32_t)tl[k * 72 + lr] | ((uint32_t)tl[(k + 1) * 72 + lr] << 16);
        }
        ((uint4*)oh)[v] = make_uint4(wh[0], wh[1], wh[2], wh[3]);
        ((uint4*)ol)[v] = make_uint4(wl[0], wl[1], wl[2], wl[3]);
    }
}

// ---------------------------------------------------------------------------
// bf16-split GEMM machinery (shared by QKV-fused and QE/Wo kernels)
// ---------------------------------------------------------------------------
#define PITCH   40
#define A_HI_O  0
#define A_LO_O  (128 * PITCH)
#define B_HI_O  (2 * 128 * PITCH)
#define B_LO_O  (3 * 128 * PITCH)
#define STAGE_E (4 * 128 * PITCH)
#define SMEM_DYN (2 * STAGE_E * 2)

#define GISSUE(c) do { \
    const uint32_t sb_ = smb + (uint32_t)(((c) & 1) * (STAGE_E * 2)); \
    const size_t ka_ = a_off + (size_t)(c) * 32; \
    const size_t kb_ = b_off + (size_t)(c) * 32; \
    cp16(sb_ + (A_HI_O + s_off) * 2,      Ahi + ka_); \
    cp16(sb_ + (A_HI_O + s_off) * 2 + 16, Ahi + ka_ + 8); \
    cp16(sb_ + (A_LO_O + s_off) * 2,      Alo + ka_); \
    cp16(sb_ + (A_LO_O + s_off) * 2 + 16, Alo + ka_ + 8); \
    cp16(sb_ + (B_HI_O + s_off) * 2,      Bhi + kb_); \
    cp16(sb_ + (B_HI_O + s_off) * 2 + 16, Bhi + kb_ + 8); \
    cp16(sb_ + (B_LO_O + s_off) * 2,      Blo + kb_); \
    cp16(sb_ + (B_LO_O + s_off) * 2 + 16, Blo + kb_ + 8); \
} while (0)

// Mainloop body shared via macro: computes acc[2][8][4] over KT.
#define GEMM_MAINLOOP(KT) do { \
    const int nch = (KT) >> 5; \
    GISSUE(0); \
    cp_commit(); \
    for (int c = 0; c < nch; c++) { \
        if (c + 1 < nch) { GISSUE(c + 1); cp_commit(); cp_wait<1>(); } \
        else             { cp_wait<0>(); } \
        __syncthreads(); \
        const uint32_t stb = smb + (uint32_t)((c & 1) * (STAGE_E * 2)); \
        _Pragma("unroll") \
        for (int kk = 0; kk < 32; kk += 16) { \
            uint32_t ah[2][4], al[2][4]; \
            _Pragma("unroll") \
            for (int mt = 0; mt < 2; mt++) { \
                const uint32_t aoff = \
                    (uint32_t)((warp_m * 32 + mt * 16 + lrow16) * PITCH + kk + lcol8) * 2; \
                ldsm4(stb + A_HI_O * 2 + aoff, ah[mt][0], ah[mt][1], ah[mt][2], ah[mt][3]); \
                ldsm4(stb + A_LO_O * 2 + aoff, al[mt][0], al[mt][1], al[mt][2], al[mt][3]); \
            } \
            uint32_t bh[8][2], bl[8][2]; \
            _Pragma("unroll") \
            for (int grp = 0; grp < 4; grp++) { \
                const uint32_t boff = \
                    (uint32_t)((warp_n * 64 + grp * 16 + lrow16) * PITCH + kk + lcol8) * 2; \
                uint32_t r0, r1, r2, r3; \
                ldsm4(stb + B_HI_O * 2 + boff, r0, r1, r2, r3); \
                bh[grp * 2][0] = r0; bh[grp * 2][1] = r2; \
                bh[grp * 2 + 1][0] = r1; bh[grp * 2 + 1][1] = r3; \
                ldsm4(stb + B_LO_O * 2 + boff, r0, r1, r2, r3); \
                bl[grp * 2][0] = r0; bl[grp * 2][1] = r2; \
                bl[grp * 2 + 1][0] = r1; bl[grp * 2 + 1][1] = r3; \
            } \
            _Pragma("unroll") \
            for (int mt = 0; mt < 2; mt++) \
                _Pragma("unroll") \
                for (int nt = 0; nt < 8; nt++) { \
                    MMA_BF16(acc[mt][nt], ah[mt], bh[nt]); \
                    MMA_BF16(acc[mt][nt], ah[mt], bl[nt]); \
                    MMA_BF16(acc[mt][nt], al[mt], bh[nt]); \
                } \
        } \
        __syncthreads(); \
    } \
} while (0)

// QKV projections fused over blockIdx.z; writes bf16 hi/lo head layout.
__global__ __launch_bounds__(256) void ra_mma_gemm_qkv(
    const unsigned short* __restrict__ XhB, const unsigned short* __restrict__ XlB,
    const unsigned short* __restrict__ BhB, const unsigned short* __restrict__ BlB,
    const float* __restrict__ bq, const float* __restrict__ bk,
    const float* __restrict__ bv,
    unsigned short* __restrict__ Qh, unsigned short* __restrict__ Ql,
    unsigned short* __restrict__ Kh, unsigned short* __restrict__ Kl,
    unsigned short* __restrict__ Vh, unsigned short* __restrict__ Vl)
{
    const int z = blockIdx.z;
    const unsigned short* Ahi = XhB + (size_t)z * (NLROWS * DMODEL);
    const unsigned short* Alo = XlB + (size_t)z * (NLROWS * DMODEL);
    const unsigned short* Bhi = BhB + (size_t)z * (DMODEL * DMODEL);
    const unsigned short* Blo = BlB + (size_t)z * (DMODEL * DMODEL);
    const float* bias = z == 0 ? bq : (z == 1 ? bk : bv);
    unsigned short* outh = z == 0 ? Qh : (z == 1 ? Kh : Vh);
    unsigned short* outl = z == 0 ? Ql : (z == 1 ? Kl : Vl);
    const float scale = (z == 0) ? 0.125f : 1.0f;

    const int m0 = blockIdx.y * 128;
    const int n0 = blockIdx.x * 128;
    extern __shared__ unsigned short sm[];
    const uint32_t smb = smem_u32(sm);

    const int tid    = threadIdx.x;
    const int wid    = tid >> 5;
    const int lane   = tid & 31;
    const int warp_m = wid & 3;
    const int warp_n = wid >> 2;
    const int lrow16 = lane & 15;
    const int lcol8  = (lane >> 4) << 3;

    const int glr = tid >> 1;
    const int glc = (tid & 1) * 16;
    const size_t a_off = (size_t)(m0 + glr) * DMODEL + glc;
    const size_t b_off = (size_t)(n0 + glr) * DMODEL + glc;
    const int    s_off = glr * PITCH + glc;

    float acc[2][8][4];
    #pragma unroll
    for (int mt = 0; mt < 2; mt++)
        #pragma unroll
        for (int nt = 0; nt < 8; nt++)
            #pragma unroll
            for (int i = 0; i < 4; i++) acc[mt][nt][i] = 0.f;

    GEMM_MAINLOOP(DMODEL);

    // Epilogue: bf16 hi/lo head layout
    const int rbase = m0 + warp_m * 32 + (lane >> 2);
    const int cbase = n0 + warp_n * 64 + (lane & 3) * 2;
    #pragma unroll
    for (int mt = 0; mt < 2; mt++) {
        #pragma unroll
        for (int nt = 0; nt < 8; nt++) {
            const int col = cbase + nt * 8;
            const float b0 = bias[col], b1 = bias[col + 1];
            #pragma unroll
            for (int half = 0; half < 2; half++) {
                const int row = rbase + mt * 16 + half * 8;
                const float v0 = (acc[mt][nt][half * 2 + 0] + b0) * scale;
                const float v1 = (acc[mt][nt][half * 2 + 1] + b1) * scale;
                const int n = row >> 10, l = row & (SEQL - 1);
                const int h = (col >> 6) & (NHEADS - 1);
                const size_t oidx =
                    ((size_t)((n * NHEADS + h) * SEQL + l)) * DEPTH + (col & 63);
                const uint32_t hp = packbf(v0, v1);
                *(uint32_t*)(outh + oidx) = hp;
                *(uint32_t*)(outl + oidx) =
                    packbf(v0 - __uint_as_float(hp << 16),
                           v1 - __uint_as_float(hp & 0xffff0000u));
            }
        }
    }
}

// QE band (omode 2, bf16 out) / Wo projection (omode 0, f32 out)
__global__ __launch_bounds__(256) void ra_mma_gemm(
    const unsigned short* __restrict__ Ahi, const unsigned short* __restrict__ Alo,
    const unsigned short* __restrict__ Bhi, const unsigned short* __restrict__ Blo,
    const float* __restrict__ bias, float* __restrict__ outf, int KT, int omode)
{
    const int m0 = blockIdx.y * 128;
    const int n0 = blockIdx.x * 128;
    if (omode == 2) {
        const int i0 = m0 & (SEQL - 1);
        if (n0 + 127 < (SEQL - 128) - i0) return;   // band never read
    }
    extern __shared__ unsigned short sm[];
    const uint32_t smb = smem_u32(sm);

    const int tid    = threadIdx.x;
    const int wid    = tid >> 5;
    const int lane   = tid & 31;
    const int warp_m = wid & 3;
    const int warp_n = wid >> 2;
    const int lrow16 = lane & 15;
    const int lcol8  = (lane >> 4) << 3;

    const int glr = tid >> 1;
    const int glc = (tid & 1) * 16;
    const size_t a_off = (size_t)(m0 + glr) * KT + glc;
    const size_t b_off = (size_t)(n0 + glr) * KT + glc;
    const int    s_off = glr * PITCH + glc;

    float acc[2][8][4];
    #pragma unroll
    for (int mt = 0; mt < 2; mt++)
        #pragma unroll
        for (int nt = 0; nt < 8; nt++)
            #pragma unroll
            for (int i = 0; i < 4; i++) acc[mt][nt][i] = 0.f;

    GEMM_MAINLOOP(KT);

    const int rbase = m0 + warp_m * 32 + (lane >> 2);
    const int cbase = n0 + warp_n * 64 + (lane & 3) * 2;
    unsigned short* ob16 = (unsigned short*)outf;   // omode 2: bf16 band
    #pragma unroll
    for (int mt = 0; mt < 2; mt++) {
        #pragma unroll
        for (int nt = 0; nt < 8; nt++) {
            const int col = cbase + nt * 8;
            const float b0 = bias[col], b1 = bias[col + 1];
            #pragma unroll
            for (int half = 0; half < 2; half++) {
                const int row = rbase + mt * 16 + half * 8;
                const float v0 = acc[mt][nt][half * 2 + 0] + b0;
                const float v1 = acc[mt][nt][half * 2 + 1] + b1;
                if (omode == 0) {
                    *(float2*)(outf + (size_t)row * DMODEL + col) = make_float2(v0, v1);
                } else {
                    const int i = row & (SEQL - 1);
                    const int j = col + i - (SEQL - 1);
                    if (j >= 0)
                        ob16[(size_t)row * SEQL + j] =
                            __bfloat16_as_ushort(__float2bfloat16(v0));
                    if (j + 1 >= 0)
                        ob16[(size_t)row * SEQL + j + 1] =
                            __bfloat16_as_ushort(__float2bfloat16(v1));
                }
            }
        }
    }
}

// ---------------------------------------------------------------------------
// MMA flash attention; QE bias now bf16 (half the stream + smaller stages).
// ---------------------------------------------------------------------------
#define AT_KHI     0
#define AT_KLO     9216
#define AT_VHI     18432
#define AT_VLO     27648
#define AT_BIAS    36864
#define AT_STAGE_B 46080               // 36864 + 64*72*2
#define AT_SMEM    (2 * AT_STAGE_B)    // 92160 bytes

__device__ __forceinline__ void attn_issue(
    uint32_t sb, int nh, int i0, int j0, int lr, int lc2,
    const unsigned short* __restrict__ Khi, const unsigned short* __restrict__ Klo,
    const unsigned short* __restrict__ Vthi, const unsigned short* __restrict__ Vtlo,
    const unsigned short* __restrict__ QE)
{
    const size_t krow = ((size_t)(nh * SEQL + j0 + lr)) * 64 + lc2;
    const size_t vrow = ((size_t)(nh * 64 + lr)) * SEQL + j0 + lc2;
    const uint32_t so = (uint32_t)(lr * 72 + lc2) * 2;
    #pragma unroll
    for (int u = 0; u < 4; u++) {
        cp16(sb + AT_KHI + so + u * 16, Khi + krow + u * 8);
        cp16(sb + AT_KLO + so + u * 16, Klo + krow + u * 8);
        cp16(sb + AT_VHI + so + u * 16, Vthi + vrow + u * 8);
        cp16(sb + AT_VLO + so + u * 16, Vtlo + vrow + u * 8);
    }
    const unsigned short* gb = QE + (size_t)(nh * SEQL + i0 + lr) * SEQL + j0 + lc2;
    const uint32_t sbia = sb + AT_BIAS + (uint32_t)(lr * 72 + lc2) * 2;
    #pragma unroll
    for (int u = 0; u < 4; u++)
        cp16(sbia + u * 16, gb + u * 8);
}

__global__ __launch_bounds__(128) void ra_attn_mma(
    const unsigned short* __restrict__ Qhi, const unsigned short* __restrict__ Qlo,
    const unsigned short* __restrict__ Khi, const unsigned short* __restrict__ Klo,
    const unsigned short* __restrict__ Vthi, const unsigned short* __restrict__ Vtlo,
    const unsigned short* __restrict__ QE,
    unsigned short* __restrict__ AOhi, unsigned short* __restrict__ AOlo)
{
    extern __shared__ char smc[];
    const uint32_t smb = smem_u32(smc);
    const int nh = blockIdx.y;
    const int i0 = (int)(gridDim.x - 1 - blockIdx.x) * 64;
    const int t = threadIdx.x;
    const int w = t >> 5, lane = t & 31;
    const int g = lane >> 2, q4 = lane & 3;
    const int lr = t >> 1, lc2 = (t & 1) * 32;
    const int lrow16 = lane & 15, lcol8 = (lane >> 4) << 3;
    const int ntj = i0 >> 6;

    attn_issue(smb, nh, i0, 0, lr, lc2, Khi, Klo, Vthi, Vtlo, QE);
    cp_commit();

    uint32_t qh[4][4], ql[4][4];
    {
        const uint4* src = (const uint4*)(Qhi + ((size_t)(nh * SEQL + i0 + lr)) * 64 + lc2);
        uint4* dst = (uint4*)(smc + AT_STAGE_B + (lr * 72 + lc2) * 2);
        #pragma unroll
        for (int u = 0; u < 4; u++) dst[u] = src[u];
    }
    __syncthreads();
    #pragma unroll
    for (int kt = 0; kt < 4; kt++)
        ldsm4(smb + AT_STAGE_B + (uint32_t)((16 * w + lrow16) * 72 + kt * 16 + lcol8) * 2,
              qh[kt][0], qh[kt][1], qh[kt][2], qh[kt][3]);
    __syncthreads();
    {
        const uint4* src = (const uint4*)(Qlo + ((size_t)(nh * SEQL + i0 + lr)) * 64 + lc2);
        uint4* dst = (uint4*)(smc + AT_STAGE_B + (lr * 72 + lc2) * 2);
        #pragma unroll
        for (int u = 0; u < 4; u++) dst[u] = src[u];
    }
    __syncthreads();
    #pragma unroll
    for (int kt = 0; kt < 4; kt++)
        ldsm4(smb + AT_STAGE_B + (uint32_t)((16 * w + lrow16) * 72 + kt * 16 + lcol8) * 2,
              ql[kt][0], ql[kt][1], ql[kt][2], ql[kt][3]);
    __syncthreads();

    float o[8][4];
    #pragma unroll
    for (int nt = 0; nt < 8; nt++)
        #pragma unroll
        for (int i = 0; i < 4; i++) o[nt][i] = 0.f;
    float rm[2] = {-1e30f, -1e30f};
    float rl[2] = {0.f, 0.f};

    for (int c = 0; c <= ntj; c++) {
        if (c < ntj) {
            attn_issue(smb + (uint32_t)(((c + 1) & 1) * AT_STAGE_B),
                       nh, i0, (c + 1) * 64, lr, lc2, Khi, Klo, Vthi, Vtlo, QE);
            cp_commit();
            cp_wait<1>();
        } else {
            cp_wait<0>();
        }
        __syncthreads();

        const uint32_t stg = smb + (uint32_t)((c & 1) * AT_STAGE_B);
        const char* stgc = smc + (size_t)((c & 1) * AT_STAGE_B);

        float s[8][4];
        #pragma unroll
        for (int nt = 0; nt < 8; nt++)
            #pragma unroll
            for (int i = 0; i < 4; i++) s[nt][i] = 0.f;
        #pragma unroll
        for (int kt = 0; kt < 4; kt++) {
            uint32_t kbh[8][2], kbl[8][2];
            #pragma unroll
            for (int grp = 0; grp < 4; grp++) {
                const uint32_t off = (uint32_t)((grp * 16 + lrow16) * 72 + kt * 16 + lcol8) * 2;
                uint32_t r0, r1, r2, r3;
                ldsm4(stg + AT_KHI + off, r0, r1, r2, r3);
                kbh[grp * 2][0] = r0; kbh[grp * 2][1] = r2;
                kbh[grp * 2 + 1][0] = r1; kbh[grp * 2 + 1][1] = r3;
                ldsm4(stg + AT_KLO + off, r0, r1, r2, r3);
                kbl[grp * 2][0] = r0; kbl[grp * 2][1] = r2;
                kbl[grp * 2 + 1][0] = r1; kbl[grp * 2 + 1][1] = r3;
            }
            #pragma unroll
            for (int nt = 0; nt < 8; nt++) {
                MMA_BF16(s[nt], qh[kt], kbh[nt]);
                MMA_BF16(s[nt], qh[kt], kbl[nt]);
                MMA_BF16(s[nt], ql[kt], kbh[nt]);
            }
        }

        const int r0l = 16 * w + g, r1l = r0l + 8;
        #pragma unroll
        for (int nt = 0; nt < 8; nt++) {
            const int cl = nt * 8 + q4 * 2;
            const uint32_t b0 = *(const uint32_t*)(stgc + AT_BIAS + (r0l * 72 + cl) * 2);
            const uint32_t b1 = *(const uint32_t*)(stgc + AT_BIAS + (r1l * 72 + cl) * 2);
            s[nt][0] += __uint_as_float(b0 << 16);
            s[nt][1] += __uint_as_float(b0 & 0xffff0000u);
            s[nt][2] += __uint_as_float(b1 << 16);
            s[nt][3] += __uint_as_float(b1 & 0xffff0000u);
        }
        if (c == ntj) {
            #pragma unroll
            for (int nt = 0; nt < 8; nt++) {
                const int cl = nt * 8 + q4 * 2;
                if (cl     > r0l) s[nt][0] = -1e30f;
                if (cl + 1 > r0l) s[nt][1] = -1e30f;
                if (cl     > r1l) s[nt][2] = -1e30f;
                if (cl + 1 > r1l) s[nt][3] = -1e30f;
            }
        }

        float mx0 = -1e30f, mx1 = -1e30f;
        #pragma unroll
        for (int nt = 0; nt < 8; nt++) {
            mx0 = fmaxf(mx0, fmaxf(s[nt][0], s[nt][1]));
            mx1 = fmaxf(mx1, fmaxf(s[nt][2], s[nt][3]));
        }
        mx0 = fmaxf(mx0, __shfl_xor_sync(0xffffffffu, mx0, 1));
        mx0 = fmaxf(mx0, __shfl_xor_sync(0xffffffffu, mx0, 2));
        mx1 = fmaxf(mx1, __shfl_xor_sync(0xffffffffu, mx1, 1));
        mx1 = fmaxf(mx1, __shfl_xor_sync(0xffffffffu, mx1, 2));
        const float m0n = fmaxf(rm[0], mx0);
        const float m1n = fmaxf(rm[1], mx1);
        const float a0 = __expf(rm[0] - m0n);
        const float a1 = __expf(rm[1] - m1n);
        float ps0 = 0.f, ps1 = 0.f;
        uint32_t ph[4][4], pl[4][4];
        #pragma unroll
        for (int nt = 0; nt < 8; nt++) {
            const float p0 = __expf(s[nt][0] - m0n);
            const float p1 = __expf(s[nt][1] - m0n);
            const float p2 = __expf(s[nt][2] - m1n);
            const float p3 = __expf(s[nt][3] - m1n);
            ps0 += p0 + p1; ps1 += p2 + p3;
            const int kt = nt >> 1, sl = (nt & 1) * 2;
            const uint32_t hp01 = packbf(p0, p1);
            const uint32_t hp23 = packbf(p2, p3);
            ph[kt][sl + 0] = hp01;
            ph[kt][sl + 1] = hp23;
            pl[kt][sl + 0] = packbf(p0 - __uint_as_float(hp01 << 16),
                                    p1 - __uint_as_float(hp01 & 0xffff0000u));
            pl[kt][sl + 1] = packbf(p2 - __uint_as_float(hp23 << 16),
                                    p3 - __uint_as_float(hp23 & 0xffff0000u));
        }
        ps0 += __shfl_xor_sync(0xffffffffu, ps0, 1);
        ps0 += __shfl_xor_sync(0xffffffffu, ps0, 2);
        ps1 += __shfl_xor_sync(0xffffffffu, ps1, 1);
        ps1 += __shfl_xor_sync(0xffffffffu, ps1, 2);
        rl[0] = rl[0] * a0 + ps0;
        rl[1] = rl[1] * a1 + ps1;
        rm[0] = m0n; rm[1] = m1n;
        #pragma unroll
        for (int nt = 0; nt < 8; nt++) {
            o[nt][0] *= a0; o[nt][1] *= a0;
            o[nt][2] *= a1; o[nt][3] *= a1;
        }

        #pragma unroll
        for (int kt = 0; kt < 4; kt++) {
            uint32_t vbh[8][2], vbl[8][2];
            #pragma unroll
            for (int grp = 0; grp < 4; grp++) {
                const uint32_t off = (uint32_t)((grp * 16 + lrow16) * 72 + kt * 16 + lcol8) * 2;
                uint32_t r0, r1, r2, r3;
                ldsm4(stg + AT_VHI + off, r0, r1, r2, r3);
                vbh[grp * 2][0] = r0; vbh[grp * 2][1] = r2;
                vbh[grp * 2 + 1][0] = r1; vbh[grp * 2 + 1][1] = r3;
                ldsm4(stg + AT_VLO + off, r0, r1, r2, r3);
                vbl[grp * 2][0] = r0; vbl[grp * 2][1] = r2;
                vbl[grp * 2 + 1][0] = r1; vbl[grp * 2 + 1][1] = r3;
            }
            #pragma unroll
            for (int nt = 0; nt < 8; nt++) {
                MMA_BF16(o[nt], ph[kt], vbh[nt]);
                MMA_BF16(o[nt], ph[kt], vbl[nt]);
                MMA_BF16(o[nt], pl[kt], vbh[nt]);
            }
        }
        __syncthreads();
    }

    const float inv0 = 1.f / rl[0], inv1 = 1.f / rl[1];
    const int n = nh >> 4, h = nh & (NHEADS - 1);
    const int r0g = i0 + 16 * w + g, r1g = r0g + 8;
    #pragma unroll
    for (int nt = 0; nt < 8; nt++) {
        const int col = h * 64 + nt * 8 + q4 * 2;
        const float v0 = o[nt][0] * inv0, v1 = o[nt][1] * inv0;
        const float v2 = o[nt][2] * inv1, v3 = o[nt][3] * inv1;
        const size_t idx0 = ((size_t)(n * SEQL + r0g)) * DMODEL + col;
        const size_t idx1 = ((size_t)(n * SEQL + r1g)) * DMODEL + col;
        const uint32_t hp01 = packbf(v0, v1);
        const uint32_t hp23 = packbf(v2, v3);
        *(uint32_t*)(AOhi + idx0) = hp01;
        *(uint32_t*)(AOhi + idx1) = hp23;
        *(uint32_t*)(AOlo + idx0) = packbf(v0 - __uint_as_float(hp01 << 16),
                                           v1 - __uint_as_float(hp01 & 0xffff0000u));
        *(uint32_t*)(AOlo + idx1) = packbf(v2 - __uint_as_float(hp23 << 16),
                                           v3 - __uint_as_float(hp23 & 0xffff0000u));
    }
}

// ---------------------------------------------------------------------------
extern "C" void kernel_launch(void* const* d_in, const int* in_sizes, int n_in,
                              void* d_out, int out_size)
{
    (void)in_sizes; (void)n_in; (void)out_size;
    const float* q_in    = (const float*)d_in[0];
    const float* k_in    = (const float*)d_in[1];
    const float* v_in    = (const float*)d_in[2];
    /* d_in[3] = mask (triu k=1) — handled analytically */
    const float* Wq      = (const float*)d_in[4];
    const float* bq      = (const float*)d_in[5];
    const float* Wk      = (const float*)d_in[6];
    const float* bk      = (const float*)d_in[7];
    const float* Wv      = (const float*)d_in[8];
    const float* bv      = (const float*)d_in[9];
    const float* Wo      = (const float*)d_in[10];
    const float* bo      = (const float*)d_in[11];
    const float* pos_emb = (const float*)d_in[12];

    unsigned short* QEp;
    float* zb;
    unsigned short (*Xh)[NLROWS * DMODEL], (*Xl)[NLROWS * DMODEL];
    unsigned short (*Bh)[DMODEL * DMODEL], (*Bl)[DMODEL * DMODEL];
    unsigned short *Eh, *El, *Qh, *Ql, *Kh, *Kl, *Vh, *Vl, *Vth, *Vtl;
    cudaGetSymbolAddress((void**)&QEp, g_QE);
    cudaGetSymbolAddress((void**)&zb,  g_zbias);
    cudaGetSymbolAddress((void**)&Xh,  g_Xhi);
    cudaGetSymbolAddress((void**)&Xl,  g_Xlo);
    cudaGetSymbolAddress((void**)&Bh,  g_Bhi);
    cudaGetSymbolAddress((void**)&Bl,  g_Blo);
    cudaGetSymbolAddress((void**)&Eh,  g_Ehi);
    cudaGetSymbolAddress((void**)&El,  g_Elo);
    cudaGetSymbolAddress((void**)&Qh,  g_Qhi);
    cudaGetSymbolAddress((void**)&Ql,  g_Qlo);
    cudaGetSymbolAddress((void**)&Kh,  g_Khi);
    cudaGetSymbolAddress((void**)&Kl,  g_Klo);
    cudaGetSymbolAddress((void**)&Vh,  g_Vhi);
    cudaGetSymbolAddress((void**)&Vl,  g_Vlo);
    cudaGetSymbolAddress((void**)&Vth, g_Vthi);
    cudaGetSymbolAddress((void**)&Vtl, g_Vtlo);

    cudaFuncSetAttribute(ra_mma_gemm, cudaFuncAttributeMaxDynamicSharedMemorySize,
                         SMEM_DYN);
    cudaFuncSetAttribute(ra_mma_gemm_qkv, cudaFuncAttributeMaxDynamicSharedMemorySize,
                         SMEM_DYN);
    cudaFuncSetAttribute(ra_attn_mma, cudaFuncAttributeMaxDynamicSharedMemorySize,
                         AT_SMEM);

    const int n4x = (NLROWS * DMODEL) / 4;

    // All conversions up front (fused launches)
    ra_conv_hilo3<<<dim3(n4x / 256, 3), 256>>>(q_in, k_in, v_in,
                                               Xh[0], Xl[0], Xh[1], Xl[1],
                                               Xh[2], Xl[2], n4x);
    ra_conv_wt4<<<dim3(32, 32, 4), dim3(32, 8)>>>(Wq, Wk, Wv, Wo,
                                                  Bh[0], Bl[0], Bh[1], Bl[1],
                                                  Bh[2], Bl[2], Bh[3], Bl[3]);
    ra_conv_hilo<<<(SEQL * DEPTH / 4) / 256, 256>>>(pos_emb + SEQL * DEPTH,
                                                    Eh, El, SEQL * DEPTH / 4);

    // Q/K/V projections fused into one launch (Q carries 1/sqrt(d))
    ra_mma_gemm_qkv<<<dim3(DMODEL / 128, NLROWS / 128, 3), 256, SMEM_DYN>>>(
        Xh[0], Xl[0], Bh[0], Bl[0], bq, bk, bv, Qh, Ql, Kh, Kl, Vh, Vl);
    ra_vt<<<dim3(16, NHTOT), 128>>>(Vh, Vl, Vth, Vtl);

    // QE = Q @ E^T (K=64), diag-shifted band, bf16 output
    ra_mma_gemm<<<dim3(SEQL / 128, QROWS / 128), 256, SMEM_DYN>>>(
        Qh, Ql, Eh, El, zb, (float*)QEp, DEPTH, 2);

    // Pipelined MMA flash attention -> AO hi/lo (reuses X[0])
    ra_attn_mma<<<dim3(SEQL / 64, NHTOT), 128, AT_SMEM>>>(
        Qh, Ql, Kh, Kl, Vth, Vtl, QEp, Xh[0], Xl[0]);

    // Output projection -> f32 d_out
    ra_mma_gemm<<<dim3(DMODEL / 128, NLROWS / 128), 256, SMEM_DYN>>>(
        Xh[0], Xl[0], Bh[3], Bl[3], bo, (float*)d_out, DMODEL, 0);
}

// round 13
// speedup vs baseline: 1.0023x; 1.0023x over previous
#include <cuda_runtime.h>
#include <cuda_bf16.h>
#include <cstdint>

// Problem constants
#define SEQL   1024
#define DMODEL 1024
#define NBATCH 4
#define NHEADS 16
#define DEPTH  64
#define NHTOT  (NBATCH * NHEADS)   // 64
#define NLROWS (NBATCH * SEQL)     // 4096
#define QROWS  (NHTOT * SEQL)      // 65536

// ---------------------------------------------------------------------------
// Scratch (device globals; allocation-free per harness rules)
// ---------------------------------------------------------------------------
__device__ __align__(128) unsigned short g_QE[(size_t)QROWS * SEQL]; // bf16 diag-shifted band
__device__ float g_zbias[DMODEL];                                   // zero-initialized
// bf16 hi/lo split buffers
__device__ __align__(128) unsigned short g_Xhi[3][NLROWS * DMODEL]; // q/k/v ins; [0] reused for AO
__device__ __align__(128) unsigned short g_Xlo[3][NLROWS * DMODEL];
__device__ __align__(128) unsigned short g_Bhi[4][DMODEL * DMODEL]; // Wq/Wk/Wv/Wo ^T
__device__ __align__(128) unsigned short g_Blo[4][DMODEL * DMODEL];
__device__ __align__(128) unsigned short g_Ehi[SEQL * DEPTH];
__device__ __align__(128) unsigned short g_Elo[SEQL * DEPTH];
__device__ __align__(128) unsigned short g_Qhi[QROWS * DEPTH];
__device__ __align__(128) unsigned short g_Qlo[QROWS * DEPTH];
__device__ __align__(128) unsigned short g_Khi[QROWS * DEPTH];
__device__ __align__(128) unsigned short g_Klo[QROWS * DEPTH];
__device__ __align__(128) unsigned short g_Vhi[QROWS * DEPTH];
__device__ __align__(128) unsigned short g_Vlo[QROWS * DEPTH];
__device__ __align__(128) unsigned short g_Vthi[QROWS * DEPTH]; // [nh][64 d][1024 key]
__device__ __align__(128) unsigned short g_Vtlo[QROWS * DEPTH];

// ---------------------------------------------------------------------------
// Helpers
// ---------------------------------------------------------------------------
__device__ __forceinline__ uint32_t smem_u32(const void* p) {
    uint32_t a;
    asm("{ .reg .u64 t; cvta.to.shared.u64 t, %1; cvt.u32.u64 %0, t; }"
        : "=r"(a) : "l"(p));
    return a;
}
__device__ __forceinline__ uint32_t packbf(float a, float b) {
    __nv_bfloat162 t = __floats2bfloat162_rn(a, b);   // x=a (low), y=b (high)
    return *reinterpret_cast<uint32_t*>(&t);
}
__device__ __forceinline__ void ldsm4(uint32_t addr, uint32_t& r0, uint32_t& r1,
                                      uint32_t& r2, uint32_t& r3) {
    asm volatile("ldmatrix.sync.aligned.m8n8.x4.shared.b16 {%0,%1,%2,%3}, [%4];"
                 : "=r"(r0), "=r"(r1), "=r"(r2), "=r"(r3) : "r"(addr));
}
__device__ __forceinline__ void cp16(uint32_t saddr, const void* g) {
    asm volatile("cp.async.cg.shared.global [%0], [%1], 16;"
                 :: "r"(saddr), "l"(g) : "memory");
}
__device__ __forceinline__ void cp_commit() {
    asm volatile("cp.async.commit_group;" ::: "memory");
}
template <int N>
__device__ __forceinline__ void cp_wait() {
    asm volatile("cp.async.wait_group %0;" :: "n"(N) : "memory");
}
#define MMA_BF16(c, a, b) \
    asm volatile("mma.sync.aligned.m16n8k16.row.col.f32.bf16.bf16.f32 " \
                 "{%0,%1,%2,%3}, {%4,%5,%6,%7}, {%8,%9}, {%0,%1,%2,%3};" \
                 : "+f"((c)[0]), "+f"((c)[1]), "+f"((c)[2]), "+f"((c)[3]) \
                 : "r"((a)[0]), "r"((a)[1]), "r"((a)[2]), "r"((a)[3]), \
                   "r"((b)[0]), "r"((b)[1]))

// ---------------------------------------------------------------------------
// Conversion kernels (fused multi-tensor variants)
// ---------------------------------------------------------------------------
__global__ __launch_bounds__(256) void ra_conv_hilo3(
    const float* __restrict__ x0, const float* __restrict__ x1,
    const float* __restrict__ x2,
    unsigned short* __restrict__ h0, unsigned short* __restrict__ l0,
    unsigned short* __restrict__ h1, unsigned short* __restrict__ l1,
    unsigned short* __restrict__ h2, unsigned short* __restrict__ l2, int n4)
{
    const int z = blockIdx.y;
    const float* x = z == 0 ? x0 : (z == 1 ? x1 : x2);
    unsigned short* hi = z == 0 ? h0 : (z == 1 ? h1 : h2);
    unsigned short* lo = z == 0 ? l0 : (z == 1 ? l1 : l2);
    int i = blockIdx.x * 256 + threadIdx.x;
    if (i >= n4) return;
    float4 v = ((const float4*)x)[i];
    uint32_t hp0 = packbf(v.x, v.y);
    uint32_t hp1 = packbf(v.z, v.w);
    uint32_t lp0 = packbf(v.x - __uint_as_float(hp0 << 16),
                          v.y - __uint_as_float(hp0 & 0xffff0000u));
    uint32_t lp1 = packbf(v.z - __uint_as_float(hp1 << 16),
                          v.w - __uint_as_float(hp1 & 0xffff0000u));
    ((uint2*)hi)[i] = make_uint2(hp0, hp1);
    ((uint2*)lo)[i] = make_uint2(lp0, lp1);
}

__global__ __launch_bounds__(256) void ra_conv_hilo(
    const float* __restrict__ x, unsigned short* __restrict__ hi,
    unsigned short* __restrict__ lo, int n4)
{
    int i = blockIdx.x * 256 + threadIdx.x;
    if (i >= n4) return;
    float4 v = ((const float4*)x)[i];
    uint32_t hp0 = packbf(v.x, v.y);
    uint32_t hp1 = packbf(v.z, v.w);
    uint32_t lp0 = packbf(v.x - __uint_as_float(hp0 << 16),
                          v.y - __uint_as_float(hp0 & 0xffff0000u));
    uint32_t lp1 = packbf(v.z - __uint_as_float(hp1 << 16),
                          v.w - __uint_as_float(hp1 & 0xffff0000u));
    ((uint2*)hi)[i] = make_uint2(hp0, hp1);
    ((uint2*)lo)[i] = make_uint2(lp0, lp1);
}

// W [K=1024, N=1024] -> W^T hi/lo bf16 [N, K]; 4 weights fused via blockIdx.z
__global__ __launch_bounds__(256) void ra_conv_wt4(
    const float* __restrict__ W0, const float* __restrict__ W1,
    const float* __restrict__ W2, const float* __restrict__ W3,
    unsigned short* __restrict__ h0, unsigned short* __restrict__ l0,
    unsigned short* __restrict__ h1, unsigned short* __restrict__ l1,
    unsigned short* __restrict__ h2, unsigned short* __restrict__ l2,
    unsigned short* __restrict__ h3, unsigned short* __restrict__ l3)
{
    const int z = blockIdx.z;
    const float* W = z == 0 ? W0 : (z == 1 ? W1 : (z == 2 ? W2 : W3));
    unsigned short* hiT = z == 0 ? h0 : (z == 1 ? h1 : (z == 2 ? h2 : h3));
    unsigned short* loT = z == 0 ? l0 : (z == 1 ? l1 : (z == 2 ? l2 : l3));
    __shared__ float tile[32][33];
    const int nx = blockIdx.x * 32 + threadIdx.x;
    const int k0 = blockIdx.y * 32;
    #pragma unroll
    for (int r = 0; r < 4; r++)
        tile[threadIdx.y + r * 8][threadIdx.x] =
            W[(size_t)(k0 + threadIdx.y + r * 8) * DMODEL + nx];
    __syncthreads();
    const int kx = k0 + threadIdx.x;
    const int n0 = blockIdx.x * 32;
    #pragma unroll
    for (int r = 0; r < 4; r++) {
        float v = tile[threadIdx.x][threadIdx.y + r * 8];
        __nv_bfloat16 hb = __float2bfloat16(v);
        __nv_bfloat16 lb = __float2bfloat16(v - __bfloat162float(hb));
        size_t o = (size_t)(n0 + threadIdx.y + r * 8) * DMODEL + kx;
        hiT[o] = __bfloat16_as_ushort(hb);
        loT[o] = __bfloat16_as_ushort(lb);
    }
}

// V [nh][1024 key][64 d] hi/lo -> Vt [nh][64 d][1024 key] hi/lo
__global__ __launch_bounds__(128) void ra_vt(
    const unsigned short* __restrict__ Vhi, const unsigned short* __restrict__ Vlo,
    unsigned short* __restrict__ Vthi, unsigned short* __restrict__ Vtlo)
{
    __shared__ unsigned short th[64 * 72];
    __shared__ unsigned short tl[64 * 72];
    const int head = blockIdx.y, kt = blockIdx.x;
    const int t = threadIdx.x, lr = t >> 1, lc = (t & 1) * 32;
    {
        const uint4* sh = (const uint4*)(Vhi + ((size_t)(head * SEQL + kt * 64 + lr)) * 64 + lc);
        const uint4* sl = (const uint4*)(Vlo + ((size_t)(head * SEQL + kt * 64 + lr)) * 64 + lc);
        uint4* dh = (uint4*)(th + lr * 72 + lc);
        uint4* dl = (uint4*)(tl + lr * 72 + lc);
        #pragma unroll
        for (int u = 0; u < 4; u++) { dh[u] = sh[u]; dl[u] = sl[u]; }
    }
    __syncthreads();
    unsigned short* oh = Vthi + ((size_t)(head * 64 + lr)) * SEQL + kt * 64 + lc;
    unsigned short* ol = Vtlo + ((size_t)(head * 64 + lr)) * SEQL + kt * 64 + lc;
    #pragma unroll
    for (int v = 0; v < 4; v++) {
        uint32_t wh[4], wl[4];
        #pragma unroll
        for (int u = 0; u < 4; u++) {
            const int k = lc + v * 8 + u * 2;
            wh[u] = (uint32_t)th[k * 72 + lr] | ((uint32_t)th[(k + 1) * 72 + lr] << 16);
            wl[u] = (uint32_t)tl[k * 72 + lr] | ((uint32_t)tl[(k + 1) * 72 + lr] << 16);
        }
        ((uint4*)oh)[v] = make_uint4(wh[0], wh[1], wh[2], wh[3]);
        ((uint4*)ol)[v] = make_uint4(wl[0], wl[1], wl[2], wl[3]);
    }
}

// ---------------------------------------------------------------------------
// bf16-split GEMM machinery (shared by QKV-fused and QE/Wo kernels)
// ---------------------------------------------------------------------------
#define PITCH   40
#define A_HI_O  0
#define A_LO_O  (128 * PITCH)
#define B_HI_O  (2 * 128 * PITCH)
#define B_LO_O  (3 * 128 * PITCH)
#define STAGE_E (4 * 128 * PITCH)
#define SMEM_DYN (2 * STAGE_E * 2)

#define GISSUE(c) do { \
    const uint32_t sb_ = smb + (uint32_t)(((c) & 1) * (STAGE_E * 2)); \
    const size_t ka_ = a_off + (size_t)(c) * 32; \
    const size_t kb_ = b_off + (size_t)(c) * 32; \
    cp16(sb_ + (A_HI_O + s_off) * 2,      Ahi + ka_); \
    cp16(sb_ + (A_HI_O + s_off) * 2 + 16, Ahi + ka_ + 8); \
    cp16(sb_ + (A_LO_O + s_off) * 2,      Alo + ka_); \
    cp16(sb_ + (A_LO_O + s_off) * 2 + 16, Alo + ka_ + 8); \
    cp16(sb_ + (B_HI_O + s_off) * 2,      Bhi + kb_); \
    cp16(sb_ + (B_HI_O + s_off) * 2 + 16, Bhi + kb_ + 8); \
    cp16(sb_ + (B_LO_O + s_off) * 2,      Blo + kb_); \
    cp16(sb_ + (B_LO_O + s_off) * 2 + 16, Blo + kb_ + 8); \
} while (0)

// Mainloop body shared via macro: computes acc[2][8][4] over KT.
#define GEMM_MAINLOOP(KT) do { \
    const int nch = (KT) >> 5; \
    GISSUE(0); \
    cp_commit(); \
    for (int c = 0; c < nch; c++) { \
        if (c + 1 < nch) { GISSUE(c + 1); cp_commit(); cp_wait<1>(); } \
        else             { cp_wait<0>(); } \
        __syncthreads(); \
        const uint32_t stb = smb + (uint32_t)((c & 1) * (STAGE_E * 2)); \
        _Pragma("unroll") \
        for (int kk = 0; kk < 32; kk += 16) { \
            uint32_t ah[2][4], al[2][4]; \
            _Pragma("unroll") \
            for (int mt = 0; mt < 2; mt++) { \
                const uint32_t aoff = \
                    (uint32_t)((warp_m * 32 + mt * 16 + lrow16) * PITCH + kk + lcol8) * 2; \
                ldsm4(stb + A_HI_O * 2 + aoff, ah[mt][0], ah[mt][1], ah[mt][2], ah[mt][3]); \
                ldsm4(stb + A_LO_O * 2 + aoff, al[mt][0], al[mt][1], al[mt][2], al[mt][3]); \
            } \
            uint32_t bh[8][2], bl[8][2]; \
            _Pragma("unroll") \
            for (int grp = 0; grp < 4; grp++) { \
                const uint32_t boff = \
                    (uint32_t)((warp_n * 64 + grp * 16 + lrow16) * PITCH + kk + lcol8) * 2; \
                uint32_t r0, r1, r2, r3; \
                ldsm4(stb + B_HI_O * 2 + boff, r0, r1, r2, r3); \
                bh[grp * 2][0] = r0; bh[grp * 2][1] = r2; \
                bh[grp * 2 + 1][0] = r1; bh[grp * 2 + 1][1] = r3; \
                ldsm4(stb + B_LO_O * 2 + boff, r0, r1, r2, r3); \
                bl[grp * 2][0] = r0; bl[grp * 2][1] = r2; \
                bl[grp * 2 + 1][0] = r1; bl[grp * 2 + 1][1] = r3; \
            } \
            _Pragma("unroll") \
            for (int mt = 0; mt < 2; mt++) \
                _Pragma("unroll") \
                for (int nt = 0; nt < 8; nt++) { \
                    MMA_BF16(acc[mt][nt], ah[mt], bh[nt]); \
                    MMA_BF16(acc[mt][nt], ah[mt], bl[nt]); \
                    MMA_BF16(acc[mt][nt], al[mt], bh[nt]); \
                } \
        } \
        __syncthreads(); \
    } \
} while (0)

// QKV projections fused over blockIdx.z; writes bf16 hi/lo head layout.
__global__ __launch_bounds__(256) void ra_mma_gemm_qkv(
    const unsigned short* __restrict__ XhB, const unsigned short* __restrict__ XlB,
    const unsigned short* __restrict__ BhB, const unsigned short* __restrict__ BlB,
    const float* __restrict__ bq, const float* __restrict__ bk,
    const float* __restrict__ bv,
    unsigned short* __restrict__ Qh, unsigned short* __restrict__ Ql,
    unsigned short* __restrict__ Kh, unsigned short* __restrict__ Kl,
    unsigned short* __restrict__ Vh, unsigned short* __restrict__ Vl)
{
    const int z = blockIdx.z;
    const unsigned short* Ahi = XhB + (size_t)z * (NLROWS * DMODEL);
    const unsigned short* Alo = XlB + (size_t)z * (NLROWS * DMODEL);
    const unsigned short* Bhi = BhB + (size_t)z * (DMODEL * DMODEL);
    const unsigned short* Blo = BlB + (size_t)z * (DMODEL * DMODEL);
    const float* bias = z == 0 ? bq : (z == 1 ? bk : bv);
    unsigned short* outh = z == 0 ? Qh : (z == 1 ? Kh : Vh);
    unsigned short* outl = z == 0 ? Ql : (z == 1 ? Kl : Vl);
    const float scale = (z == 0) ? 0.125f : 1.0f;

    const int m0 = blockIdx.y * 128;
    const int n0 = blockIdx.x * 128;
    extern __shared__ unsigned short sm[];
    const uint32_t smb = smem_u32(sm);

    const int tid    = threadIdx.x;
    const int wid    = tid >> 5;
    const int lane   = tid & 31;
    const int warp_m = wid & 3;
    const int warp_n = wid >> 2;
    const int lrow16 = lane & 15;
    const int lcol8  = (lane >> 4) << 3;

    const int glr = tid >> 1;
    const int glc = (tid & 1) * 16;
    const size_t a_off = (size_t)(m0 + glr) * DMODEL + glc;
    const size_t b_off = (size_t)(n0 + glr) * DMODEL + glc;
    const int    s_off = glr * PITCH + glc;

    float acc[2][8][4];
    #pragma unroll
    for (int mt = 0; mt < 2; mt++)
        #pragma unroll
        for (int nt = 0; nt < 8; nt++)
            #pragma unroll
            for (int i = 0; i < 4; i++) acc[mt][nt][i] = 0.f;

    GEMM_MAINLOOP(DMODEL);

    // Epilogue: bf16 hi/lo head layout
    const int rbase = m0 + warp_m * 32 + (lane >> 2);
    const int cbase = n0 + warp_n * 64 + (lane & 3) * 2;
    #pragma unroll
    for (int mt = 0; mt < 2; mt++) {
        #pragma unroll
        for (int nt = 0; nt < 8; nt++) {
            const int col = cbase + nt * 8;
            const float b0 = bias[col], b1 = bias[col + 1];
            #pragma unroll
            for (int half = 0; half < 2; half++) {
                const int row = rbase + mt * 16 + half * 8;
                const float v0 = (acc[mt][nt][half * 2 + 0] + b0) * scale;
                const float v1 = (acc[mt][nt][half * 2 + 1] + b1) * scale;
                const int n = row >> 10, l = row & (SEQL - 1);
                const int h = (col >> 6) & (NHEADS - 1);
                const size_t oidx =
                    ((size_t)((n * NHEADS + h) * SEQL + l)) * DEPTH + (col & 63);
                const uint32_t hp = packbf(v0, v1);
                *(uint32_t*)(outh + oidx) = hp;
                *(uint32_t*)(outl + oidx) =
                    packbf(v0 - __uint_as_float(hp << 16),
                           v1 - __uint_as_float(hp & 0xffff0000u));
            }
        }
    }
}

// QE band (omode 2, bf16 out) / Wo projection (omode 0, f32 out)
__global__ __launch_bounds__(256) void ra_mma_gemm(
    const unsigned short* __restrict__ Ahi, const unsigned short* __restrict__ Alo,
    const unsigned short* __restrict__ Bhi, const unsigned short* __restrict__ Blo,
    const float* __restrict__ bias, float* __restrict__ outf, int KT, int omode)
{
    const int m0 = blockIdx.y * 128;
    const int n0 = blockIdx.x * 128;
    if (omode == 2) {
        const int i0 = m0 & (SEQL - 1);
        if (n0 + 127 < (SEQL - 128) - i0) return;   // band never read
    }
    extern __shared__ unsigned short sm[];
    const uint32_t smb = smem_u32(sm);

    const int tid    = threadIdx.x;
    const int wid    = tid >> 5;
    const int lane   = tid & 31;
    const int warp_m = wid & 3;
    const int warp_n = wid >> 2;
    const int lrow16 = lane & 15;
    const int lcol8  = (lane >> 4) << 3;

    const int glr = tid >> 1;
    const int glc = (tid & 1) * 16;
    const size_t a_off = (size_t)(m0 + glr) * KT + glc;
    const size_t b_off = (size_t)(n0 + glr) * KT + glc;
    const int    s_off = glr * PITCH + glc;

    float acc[2][8][4];
    #pragma unroll
    for (int mt = 0; mt < 2; mt++)
        #pragma unroll
        for (int nt = 0; nt < 8; nt++)
            #pragma unroll
            for (int i = 0; i < 4; i++) acc[mt][nt][i] = 0.f;

    GEMM_MAINLOOP(KT);

    const int rbase = m0 + warp_m * 32 + (lane >> 2);
    const int cbase = n0 + warp_n * 64 + (lane & 3) * 2;
    unsigned short* ob16 = (unsigned short*)outf;   // omode 2: bf16 band
    #pragma unroll
    for (int mt = 0; mt < 2; mt++) {
        #pragma unroll
        for (int nt = 0; nt < 8; nt++) {
            const int col = cbase + nt * 8;
            const float b0 = bias[col], b1 = bias[col + 1];
            #pragma unroll
            for (int half = 0; half < 2; half++) {
                const int row = rbase + mt * 16 + half * 8;
                const float v0 = acc[mt][nt][half * 2 + 0] + b0;
                const float v1 = acc[mt][nt][half * 2 + 1] + b1;
                if (omode == 0) {
                    *(float2*)(outf + (size_t)row * DMODEL + col) = make_float2(v0, v1);
                } else {
                    const int i = row & (SEQL - 1);
                    const int j = col + i - (SEQL - 1);
                    if (j >= 0)
                        ob16[(size_t)row * SEQL + j] =
                            __bfloat16_as_ushort(__float2bfloat16(v0));
                    if (j + 1 >= 0)
                        ob16[(size_t)row * SEQL + j + 1] =
                            __bfloat16_as_ushort(__float2bfloat16(v1));
                }
            }
        }
    }
}

// ---------------------------------------------------------------------------
// MMA flash attention: 128-query tiles, 256 threads (8 warps), bf16 bias.
// ---------------------------------------------------------------------------
#define AT_KHI     0
#define AT_KLO     9216
#define AT_VHI     18432
#define AT_VLO     27648
#define AT_BIAS    36864
#define AT_STAGE_B 55296               // 36864 + 128*72*2
#define AT_SMEM    (2 * AT_STAGE_B)    // 110592 bytes

__device__ __forceinline__ void attn_issue(
    uint32_t sb, int nh, int i0, int j0, int tid,
    const unsigned short* __restrict__ Khi, const unsigned short* __restrict__ Klo,
    const unsigned short* __restrict__ Vthi, const unsigned short* __restrict__ Vtlo,
    const unsigned short* __restrict__ QE)
{
    // K/V: 64 rows x 64 u16 each; thread t -> row t>>2, 16-elem quarter (t&3)
    const int kr = tid >> 2, kc = (tid & 3) * 16;
    const size_t krow = ((size_t)(nh * SEQL + j0 + kr)) * 64 + kc;
    const size_t vrow = ((size_t)(nh * 64 + kr)) * SEQL + j0 + kc;
    const uint32_t so = (uint32_t)(kr * 72 + kc) * 2;
    #pragma unroll
    for (int u = 0; u < 2; u++) {
        cp16(sb + AT_KHI + so + u * 16, Khi + krow + u * 8);
        cp16(sb + AT_KLO + so + u * 16, Klo + krow + u * 8);
        cp16(sb + AT_VHI + so + u * 16, Vthi + vrow + u * 8);
        cp16(sb + AT_VLO + so + u * 16, Vtlo + vrow + u * 8);
    }
    // bias: 128 rows x 64 bf16; thread t -> row t>>1, 32-elem half (t&1)
    const int br = tid >> 1, bc = (tid & 1) * 32;
    const unsigned short* gb = QE + (size_t)(nh * SEQL + i0 + br) * SEQL + j0 + bc;
    const uint32_t sbia = sb + AT_BIAS + (uint32_t)(br * 72 + bc) * 2;
    #pragma unroll
    for (int u = 0; u < 4; u++)
        cp16(sbia + u * 16, gb + u * 8);
}

__global__ __launch_bounds__(256, 2) void ra_attn_mma(
    const unsigned short* __restrict__ Qhi, const unsigned short* __restrict__ Qlo,
    const unsigned short* __restrict__ Khi, const unsigned short* __restrict__ Klo,
    const unsigned short* __restrict__ Vthi, const unsigned short* __restrict__ Vtlo,
    const unsigned short* __restrict__ QE,
    unsigned short* __restrict__ AOhi, unsigned short* __restrict__ AOlo)
{
    extern __shared__ char smc[];
    const uint32_t smb = smem_u32(smc);
    const int nh = blockIdx.y;
    const int i0 = (int)(gridDim.x - 1 - blockIdx.x) * 128;   // big tiles first
    const int t = threadIdx.x;
    const int w = t >> 5, lane = t & 31;
    const int g = lane >> 2, q4 = lane & 3;
    const int lrow16 = lane & 15, lcol8 = (lane >> 4) << 3;
    const int ntj = (i0 >> 6) + 1;    // last j-tile index (diagonal spans 2 tiles)

    attn_issue(smb, nh, i0, 0, t, Khi, Klo, Vthi, Vtlo, QE);
    cp_commit();

    // ---- Q fragments via staging in stage-1 region (free until c=1) ----
    const int qr = t >> 1, qc = (t & 1) * 32;   // 128 rows x 64 u16
    uint32_t qh[4][4], ql[4][4];
    {
        const uint4* src = (const uint4*)(Qhi + ((size_t)(nh * SEQL + i0 + qr)) * 64 + qc);
        uint4* dst = (uint4*)(smc + AT_STAGE_B + (qr * 72 + qc) * 2);
        #pragma unroll
        for (int u = 0; u < 4; u++) dst[u] = src[u];
    }
    __syncthreads();
    #pragma unroll
    for (int kt = 0; kt < 4; kt++)
        ldsm4(smb + AT_STAGE_B + (uint32_t)((16 * w + lrow16) * 72 + kt * 16 + lcol8) * 2,
              qh[kt][0], qh[kt][1], qh[kt][2], qh[kt][3]);
    __syncthreads();
    {
        const uint4* src = (const uint4*)(Qlo + ((size_t)(nh * SEQL + i0 + qr)) * 64 + qc);
        uint4* dst = (uint4*)(smc + AT_STAGE_B + (qr * 72 + qc) * 2);
        #pragma unroll
        for (int u = 0; u < 4; u++) dst[u] = src[u];
    }
    __syncthreads();
    #pragma unroll
    for (int kt = 0; kt < 4; kt++)
        ldsm4(smb + AT_STAGE_B + (uint32_t)((16 * w + lrow16) * 72 + kt * 16 + lcol8) * 2,
              ql[kt][0], ql[kt][1], ql[kt][2], ql[kt][3]);
    __syncthreads();

    float o[8][4];
    #pragma unroll
    for (int nt = 0; nt < 8; nt++)
        #pragma unroll
        for (int i = 0; i < 4; i++) o[nt][i] = 0.f;
    float rm[2] = {-1e30f, -1e30f};
    float rl[2] = {0.f, 0.f};

    for (int c = 0; c <= ntj; c++) {
        if (c < ntj) {
            attn_issue(smb + (uint32_t)(((c + 1) & 1) * AT_STAGE_B),
                       nh, i0, (c + 1) * 64, t, Khi, Klo, Vthi, Vtlo, QE);
            cp_commit();
            cp_wait<1>();
        } else {
            cp_wait<0>();
        }
        __syncthreads();

        const uint32_t stg = smb + (uint32_t)((c & 1) * AT_STAGE_B);
        const char* stgc = smc + (size_t)((c & 1) * AT_STAGE_B);
        const int j0 = c * 64;

        // ---- S = QK^T (3-term split) ----
        float s[8][4];
        #pragma unroll
        for (int nt = 0; nt < 8; nt++)
            #pragma unroll
            for (int i = 0; i < 4; i++) s[nt][i] = 0.f;
        #pragma unroll
        for (int kt = 0; kt < 4; kt++) {
            uint32_t kbh[8][2], kbl[8][2];
            #pragma unroll
            for (int grp = 0; grp < 4; grp++) {
                const uint32_t off = (uint32_t)((grp * 16 + lrow16) * 72 + kt * 16 + lcol8) * 2;
                uint32_t r0, r1, r2, r3;
                ldsm4(stg + AT_KHI + off, r0, r1, r2, r3);
                kbh[grp * 2][0] = r0; kbh[grp * 2][1] = r2;
                kbh[grp * 2 + 1][0] = r1; kbh[grp * 2 + 1][1] = r3;
                ldsm4(stg + AT_KLO + off, r0, r1, r2, r3);
                kbl[grp * 2][0] = r0; kbl[grp * 2][1] = r2;
                kbl[grp * 2 + 1][0] = r1; kbl[grp * 2 + 1][1] = r3;
            }
            #pragma unroll
            for (int nt = 0; nt < 8; nt++) {
                MMA_BF16(s[nt], qh[kt], kbh[nt]);
                MMA_BF16(s[nt], qh[kt], kbl[nt]);
                MMA_BF16(s[nt], ql[kt], kbh[nt]);
            }
        }

        // ---- bias + causal mask ----
        const int r0l = 16 * w + g, r1l = r0l + 8;
        #pragma unroll
        for (int nt = 0; nt < 8; nt++) {
            const int cl = nt * 8 + q4 * 2;
            const uint32_t b0 = *(const uint32_t*)(stgc + AT_BIAS + (r0l * 72 + cl) * 2);
            const uint32_t b1 = *(const uint32_t*)(stgc + AT_BIAS + (r1l * 72 + cl) * 2);
            s[nt][0] += __uint_as_float(b0 << 16);
            s[nt][1] += __uint_as_float(b0 & 0xffff0000u);
            s[nt][2] += __uint_as_float(b1 << 16);
            s[nt][3] += __uint_as_float(b1 & 0xffff0000u);
        }
        if (c >= ntj - 1) {
            const int ig0 = i0 + r0l, ig1 = i0 + r1l;
            #pragma unroll
            for (int nt = 0; nt < 8; nt++) {
                const int jg = j0 + nt * 8 + q4 * 2;
                if (jg     > ig0) s[nt][0] = -1e30f;
                if (jg + 1 > ig0) s[nt][1] = -1e30f;
                if (jg     > ig1) s[nt][2] = -1e30f;
                if (jg + 1 > ig1) s[nt][3] = -1e30f;
            }
        }

        // ---- online softmax ----
        float mx0 = -1e30f, mx1 = -1e30f;
        #pragma unroll
        for (int nt = 0; nt < 8; nt++) {
            mx0 = fmaxf(mx0, fmaxf(s[nt][0], s[nt][1]));
            mx1 = fmaxf(mx1, fmaxf(s[nt][2], s[nt][3]));
        }
        mx0 = fmaxf(mx0, __shfl_xor_sync(0xffffffffu, mx0, 1));
        mx0 = fmaxf(mx0, __shfl_xor_sync(0xffffffffu, mx0, 2));
        mx1 = fmaxf(mx1, __shfl_xor_sync(0xffffffffu, mx1, 1));
        mx1 = fmaxf(mx1, __shfl_xor_sync(0xffffffffu, mx1, 2));
        const float m0n = fmaxf(rm[0], mx0);
        const float m1n = fmaxf(rm[1], mx1);
        const float a0 = __expf(rm[0] - m0n);
        const float a1 = __expf(rm[1] - m1n);
        float ps0 = 0.f, ps1 = 0.f;
        uint32_t ph[4][4], pl[4][4];
        #pragma unroll
        for (int nt = 0; nt < 8; nt++) {
            const float p0 = __expf(s[nt][0] - m0n);
            const float p1 = __expf(s[nt][1] - m0n);
            const float p2 = __expf(s[nt][2] - m1n);
            const float p3 = __expf(s[nt][3] - m1n);
            ps0 += p0 + p1; ps1 += p2 + p3;
            const int kt = nt >> 1, sl = (nt & 1) * 2;
            const uint32_t hp01 = packbf(p0, p1);
            const uint32_t hp23 = packbf(p2, p3);
            ph[kt][sl + 0] = hp01;
            ph[kt][sl + 1] = hp23;
            pl[kt][sl + 0] = packbf(p0 - __uint_as_float(hp01 << 16),
                                    p1 - __uint_as_float(hp01 & 0xffff0000u));
            pl[kt][sl + 1] = packbf(p2 - __uint_as_float(hp23 << 16),
                                    p3 - __uint_as_float(hp23 & 0xffff0000u));
        }
        ps0 += __shfl_xor_sync(0xffffffffu, ps0, 1);
        ps0 += __shfl_xor_sync(0xffffffffu, ps0, 2);
        ps1 += __shfl_xor_sync(0xffffffffu, ps1, 1);
        ps1 += __shfl_xor_sync(0xffffffffu, ps1, 2);
        rl[0] = rl[0] * a0 + ps0;
        rl[1] = rl[1] * a1 + ps1;
        rm[0] = m0n; rm[1] = m1n;
        #pragma unroll
        for (int nt = 0; nt < 8; nt++) {
            o[nt][0] *= a0; o[nt][1] *= a0;
            o[nt][2] *= a1; o[nt][3] *= a1;
        }

        // ---- O += P @ V (3-term split) ----
        #pragma unroll
        for (int kt = 0; kt < 4; kt++) {
            uint32_t vbh[8][2], vbl[8][2];
            #pragma unroll
            for (int grp = 0; grp < 4; grp++) {
                const uint32_t off = (uint32_t)((grp * 16 + lrow16) * 72 + kt * 16 + lcol8) * 2;
                uint32_t r0, r1, r2, r3;
                ldsm4(stg + AT_VHI + off, r0, r1, r2, r3);
                vbh[grp * 2][0] = r0; vbh[grp * 2][1] = r2;
                vbh[grp * 2 + 1][0] = r1; vbh[grp * 2 + 1][1] = r3;
                ldsm4(stg + AT_VLO + off, r0, r1, r2, r3);
                vbl[grp * 2][0] = r0; vbl[grp * 2][1] = r2;
                vbl[grp * 2 + 1][0] = r1; vbl[grp * 2 + 1][1] = r3;
            }
            #pragma unroll
            for (int nt = 0; nt < 8; nt++) {
                MMA_BF16(o[nt], ph[kt], vbh[nt]);
                MMA_BF16(o[nt], ph[kt], vbl[nt]);
                MMA_BF16(o[nt], pl[kt], vbh[nt]);
            }
        }
        __syncthreads();
    }

    // ---- epilogue: normalize, split, write AO hi/lo (natural layout) ----
    const float inv0 = 1.f / rl[0], inv1 = 1.f / rl[1];
    const int n = nh >> 4, h = nh & (NHEADS - 1);
    const int r0g = i0 + 16 * w + g, r1g = r0g + 8;
    #pragma unroll
    for (int nt = 0; nt < 8; nt++) {
        const int col = h * 64 + nt * 8 + q4 * 2;
        const float v0 = o[nt][0] * inv0, v1 = o[nt][1] * inv0;
        const float v2 = o[nt][2] * inv1, v3 = o[nt][3] * inv1;
        const size_t idx0 = ((size_t)(n * SEQL + r0g)) * DMODEL + col;
        const size_t idx1 = ((size_t)(n * SEQL + r1g)) * DMODEL + col;
        const uint32_t hp01 = packbf(v0, v1);
        const uint32_t hp23 = packbf(v2, v3);
        *(uint32_t*)(AOhi + idx0) = hp01;
        *(uint32_t*)(AOhi + idx1) = hp23;
        *(uint32_t*)(AOlo + idx0) = packbf(v0 - __uint_as_float(hp01 << 16),
                                           v1 - __uint_as_float(hp01 & 0xffff0000u));
        *(uint32_t*)(AOlo + idx1) = packbf(v2 - __uint_as_float(hp23 << 16),
                                           v3 - __uint_as_float(hp23 & 0xffff0000u));
    }
}

// ---------------------------------------------------------------------------
extern "C" void kernel_launch(void* const* d_in, const int* in_sizes, int n_in,
                              void* d_out, int out_size)
{
    (void)in_sizes; (void)n_in; (void)out_size;
    const float* q_in    = (const float*)d_in[0];
    const float* k_in    = (const float*)d_in[1];
    const float* v_in    = (const float*)d_in[2];
    /* d_in[3] = mask (triu k=1) — handled analytically */
    const float* Wq      = (const float*)d_in[4];
    const float* bq      = (const float*)d_in[5];
    const float* Wk      = (const float*)d_in[6];
    const float* bk      = (const float*)d_in[7];
    const float* Wv      = (const float*)d_in[8];
    const float* bv      = (const float*)d_in[9];
    const float* Wo      = (const float*)d_in[10];
    const float* bo      = (const float*)d_in[11];
    const float* pos_emb = (const float*)d_in[12];

    unsigned short* QEp;
    float* zb;
    unsigned short (*Xh)[NLROWS * DMODEL], (*Xl)[NLROWS * DMODEL];
    unsigned short (*Bh)[DMODEL * DMODEL], (*Bl)[DMODEL * DMODEL];
    unsigned short *Eh, *El, *Qh, *Ql, *Kh, *Kl, *Vh, *Vl, *Vth, *Vtl;
    cudaGetSymbolAddress((void**)&QEp, g_QE);
    cudaGetSymbolAddress((void**)&zb,  g_zbias);
    cudaGetSymbolAddress((void**)&Xh,  g_Xhi);
    cudaGetSymbolAddress((void**)&Xl,  g_Xlo);
    cudaGetSymbolAddress((void**)&Bh,  g_Bhi);
    cudaGetSymbolAddress((void**)&Bl,  g_Blo);
    cudaGetSymbolAddress((void**)&Eh,  g_Ehi);
    cudaGetSymbolAddress((void**)&El,  g_Elo);
    cudaGetSymbolAddress((void**)&Qh,  g_Qhi);
    cudaGetSymbolAddress((void**)&Ql,  g_Qlo);
    cudaGetSymbolAddress((void**)&Kh,  g_Khi);
    cudaGetSymbolAddress((void**)&Kl,  g_Klo);
    cudaGetSymbolAddress((void**)&Vh,  g_Vhi);
    cudaGetSymbolAddress((void**)&Vl,  g_Vlo);
    cudaGetSymbolAddress((void**)&Vth, g_Vthi);
    cudaGetSymbolAddress((void**)&Vtl, g_Vtlo);

    cudaFuncSetAttribute(ra_mma_gemm, cudaFuncAttributeMaxDynamicSharedMemorySize,
                         SMEM_DYN);
    cudaFuncSetAttribute(ra_mma_gemm_qkv, cudaFuncAttributeMaxDynamicSharedMemorySize,
                         SMEM_DYN);
    cudaFuncSetAttribute(ra_attn_mma, cudaFuncAttributeMaxDynamicSharedMemorySize,
                         AT_SMEM);

    const int n4x = (NLROWS * DMODEL) / 4;

    // All conversions up front (fused launches)
    ra_conv_hilo3<<<dim3(n4x / 256, 3), 256>>>(q_in, k_in, v_in,
                                               Xh[0], Xl[0], Xh[1], Xl[1],
                                               Xh[2], Xl[2], n4x);
    ra_conv_wt4<<<dim3(32, 32, 4), dim3(32, 8)>>>(Wq, Wk, Wv, Wo,
                                                  Bh[0], Bl[0], Bh[1], Bl[1],
                                                  Bh[2], Bl[2], Bh[3], Bl[3]);
    ra_conv_hilo<<<(SEQL * DEPTH / 4) / 256, 256>>>(pos_emb + SEQL * DEPTH,
                                                    Eh, El, SEQL * DEPTH / 4);

    // Q/K/V projections fused into one launch (Q carries 1/sqrt(d))
    ra_mma_gemm_qkv<<<dim3(DMODEL / 128, NLROWS / 128, 3), 256, SMEM_DYN>>>(
        Xh[0], Xl[0], Bh[0], Bl[0], bq, bk, bv, Qh, Ql, Kh, Kl, Vh, Vl);
    ra_vt<<<dim3(16, NHTOT), 128>>>(Vh, Vl, Vth, Vtl);

    // QE = Q @ E^T (K=64), diag-shifted band, bf16 output
    ra_mma_gemm<<<dim3(SEQL / 128, QROWS / 128), 256, SMEM_DYN>>>(
        Qh, Ql, Eh, El, zb, (float*)QEp, DEPTH, 2);

    // Pipelined MMA flash attention, 128-query tiles -> AO hi/lo (reuses X[0])
    ra_attn_mma<<<dim3(SEQL / 128, NHTOT), 256, AT_SMEM>>>(
        Qh, Ql, Kh, Kl, Vth, Vtl, QEp, Xh[0], Xl[0]);

    // Output projection -> f32 d_out
    ra_mma_gemm<<<dim3(DMODEL / 128, NLROWS / 128), 256, SMEM_DYN>>>(
        Xh[0], Xl[0], Bh[3], Bl[3], bo, (float*)d_out, DMODEL, 0);
}

// round 14
// speedup vs baseline: 1.0175x; 1.0152x over previous
#include <cuda_runtime.h>
#include <cuda_bf16.h>
#include <cstdint>

// Problem constants
#define SEQL   1024
#define DMODEL 1024
#define NBATCH 4
#define NHEADS 16
#define DEPTH  64
#define NHTOT  (NBATCH * NHEADS)   // 64
#define NLROWS (NBATCH * SEQL)     // 4096
#define QROWS  (NHTOT * SEQL)      // 65536

// ---------------------------------------------------------------------------
// Scratch (device globals; allocation-free per harness rules)
// ---------------------------------------------------------------------------
__device__ __align__(128) unsigned short g_QE[(size_t)QROWS * SEQL]; // bf16 diag-shifted band
__device__ float g_zbias[DMODEL];                                   // zero-initialized
// bf16 hi/lo split buffers
__device__ __align__(128) unsigned short g_Xhi[3][NLROWS * DMODEL]; // q/k/v ins; [0] reused for AO
__device__ __align__(128) unsigned short g_Xlo[3][NLROWS * DMODEL];
__device__ __align__(128) unsigned short g_Bhi[4][DMODEL * DMODEL]; // Wq/Wk/Wv/Wo ^T
__device__ __align__(128) unsigned short g_Blo[4][DMODEL * DMODEL];
__device__ __align__(128) unsigned short g_Ehi[SEQL * DEPTH];
__device__ __align__(128) unsigned short g_Elo[SEQL * DEPTH];
__device__ __align__(128) unsigned short g_Qhi[QROWS * DEPTH];
__device__ __align__(128) unsigned short g_Qlo[QROWS * DEPTH];
__device__ __align__(128) unsigned short g_Khi[QROWS * DEPTH];
__device__ __align__(128) unsigned short g_Klo[QROWS * DEPTH];
__device__ __align__(128) unsigned short g_Vhi[QROWS * DEPTH];
__device__ __align__(128) unsigned short g_Vlo[QROWS * DEPTH];
__device__ __align__(128) unsigned short g_Vthi[QROWS * DEPTH]; // [nh][64 d][1024 key]
__device__ __align__(128) unsigned short g_Vtlo[QROWS * DEPTH];

// ---------------------------------------------------------------------------
// Helpers
// ---------------------------------------------------------------------------
__device__ __forceinline__ uint32_t smem_u32(const void* p) {
    uint32_t a;
    asm("{ .reg .u64 t; cvta.to.shared.u64 t, %1; cvt.u32.u64 %0, t; }"
        : "=r"(a) : "l"(p));
    return a;
}
__device__ __forceinline__ uint32_t packbf(float a, float b) {
    __nv_bfloat162 t = __floats2bfloat162_rn(a, b);   // x=a (low), y=b (high)
    return *reinterpret_cast<uint32_t*>(&t);
}
__device__ __forceinline__ void ldsm4(uint32_t addr, uint32_t& r0, uint32_t& r1,
                                      uint32_t& r2, uint32_t& r3) {
    asm volatile("ldmatrix.sync.aligned.m8n8.x4.shared.b16 {%0,%1,%2,%3}, [%4];"
                 : "=r"(r0), "=r"(r1), "=r"(r2), "=r"(r3) : "r"(addr));
}
__device__ __forceinline__ void cp16(uint32_t saddr, const void* g) {
    asm volatile("cp.async.cg.shared.global [%0], [%1], 16;"
                 :: "r"(saddr), "l"(g) : "memory");
}
__device__ __forceinline__ void cp_commit() {
    asm volatile("cp.async.commit_group;" ::: "memory");
}
template <int N>
__device__ __forceinline__ void cp_wait() {
    asm volatile("cp.async.wait_group %0;" :: "n"(N) : "memory");
}
#define MMA_BF16(c, a, b) \
    asm volatile("mma.sync.aligned.m16n8k16.row.col.f32.bf16.bf16.f32 " \
                 "{%0,%1,%2,%3}, {%4,%5,%6,%7}, {%8,%9}, {%0,%1,%2,%3};" \
                 : "+f"((c)[0]), "+f"((c)[1]), "+f"((c)[2]), "+f"((c)[3]) \
                 : "r"((a)[0]), "r"((a)[1]), "r"((a)[2]), "r"((a)[3]), \
                   "r"((b)[0]), "r"((b)[1]))

// ---------------------------------------------------------------------------
// Conversion kernels (fused multi-tensor variants)
// ---------------------------------------------------------------------------
__global__ __launch_bounds__(256) void ra_conv_hilo3(
    const float* __restrict__ x0, const float* __restrict__ x1,
    const float* __restrict__ x2,
    unsigned short* __restrict__ h0, unsigned short* __restrict__ l0,
    unsigned short* __restrict__ h1, unsigned short* __restrict__ l1,
    unsigned short* __restrict__ h2, unsigned short* __restrict__ l2, int n4)
{
    const int z = blockIdx.y;
    const float* x = z == 0 ? x0 : (z == 1 ? x1 : x2);
    unsigned short* hi = z == 0 ? h0 : (z == 1 ? h1 : h2);
    unsigned short* lo = z == 0 ? l0 : (z == 1 ? l1 : l2);
    int i = blockIdx.x * 256 + threadIdx.x;
    if (i >= n4) return;
    float4 v = ((const float4*)x)[i];
    uint32_t hp0 = packbf(v.x, v.y);
    uint32_t hp1 = packbf(v.z, v.w);
    uint32_t lp0 = packbf(v.x - __uint_as_float(hp0 << 16),
                          v.y - __uint_as_float(hp0 & 0xffff0000u));
    uint32_t lp1 = packbf(v.z - __uint_as_float(hp1 << 16),
                          v.w - __uint_as_float(hp1 & 0xffff0000u));
    ((uint2*)hi)[i] = make_uint2(hp0, hp1);
    ((uint2*)lo)[i] = make_uint2(lp0, lp1);
}

__global__ __launch_bounds__(256) void ra_conv_hilo(
    const float* __restrict__ x, unsigned short* __restrict__ hi,
    unsigned short* __restrict__ lo, int n4)
{
    int i = blockIdx.x * 256 + threadIdx.x;
    if (i >= n4) return;
    float4 v = ((const float4*)x)[i];
    uint32_t hp0 = packbf(v.x, v.y);
    uint32_t hp1 = packbf(v.z, v.w);
    uint32_t lp0 = packbf(v.x - __uint_as_float(hp0 << 16),
                          v.y - __uint_as_float(hp0 & 0xffff0000u));
    uint32_t lp1 = packbf(v.z - __uint_as_float(hp1 << 16),
                          v.w - __uint_as_float(hp1 & 0xffff0000u));
    ((uint2*)hi)[i] = make_uint2(hp0, hp1);
    ((uint2*)lo)[i] = make_uint2(lp0, lp1);
}

// W [K=1024, N=1024] -> W^T hi/lo bf16 [N, K]; 4 weights fused via blockIdx.z
__global__ __launch_bounds__(256) void ra_conv_wt4(
    const float* __restrict__ W0, const float* __restrict__ W1,
    const float* __restrict__ W2, const float* __restrict__ W3,
    unsigned short* __restrict__ h0, unsigned short* __restrict__ l0,
    unsigned short* __restrict__ h1, unsigned short* __restrict__ l1,
    unsigned short* __restrict__ h2, unsigned short* __restrict__ l2,
    unsigned short* __restrict__ h3, unsigned short* __restrict__ l3)
{
    const int z = blockIdx.z;
    const float* W = z == 0 ? W0 : (z == 1 ? W1 : (z == 2 ? W2 : W3));
    unsigned short* hiT = z == 0 ? h0 : (z == 1 ? h1 : (z == 2 ? h2 : h3));
    unsigned short* loT = z == 0 ? l0 : (z == 1 ? l1 : (z == 2 ? l2 : l3));
    __shared__ float tile[32][33];
    const int nx = blockIdx.x * 32 + threadIdx.x;
    const int k0 = blockIdx.y * 32;
    #pragma unroll
    for (int r = 0; r < 4; r++)
        tile[threadIdx.y + r * 8][threadIdx.x] =
            W[(size_t)(k0 + threadIdx.y + r * 8) * DMODEL + nx];
    __syncthreads();
    const int kx = k0 + threadIdx.x;
    const int n0 = blockIdx.x * 32;
    #pragma unroll
    for (int r = 0; r < 4; r++) {
        float v = tile[threadIdx.x][threadIdx.y + r * 8];
        __nv_bfloat16 hb = __float2bfloat16(v);
        __nv_bfloat16 lb = __float2bfloat16(v - __bfloat162float(hb));
        size_t o = (size_t)(n0 + threadIdx.y + r * 8) * DMODEL + kx;
        hiT[o] = __bfloat16_as_ushort(hb);
        loT[o] = __bfloat16_as_ushort(lb);
    }
}

// V [nh][1024 key][64 d] hi/lo -> Vt [nh][64 d][1024 key] hi/lo
__global__ __launch_bounds__(128) void ra_vt(
    const unsigned short* __restrict__ Vhi, const unsigned short* __restrict__ Vlo,
    unsigned short* __restrict__ Vthi, unsigned short* __restrict__ Vtlo)
{
    __shared__ unsigned short th[64 * 72];
    __shared__ unsigned short tl[64 * 72];
    const int head = blockIdx.y, kt = blockIdx.x;
    const int t = threadIdx.x, lr = t >> 1, lc = (t & 1) * 32;
    {
        const uint4* sh = (const uint4*)(Vhi + ((size_t)(head * SEQL + kt * 64 + lr)) * 64 + lc);
        const uint4* sl = (const uint4*)(Vlo + ((size_t)(head * SEQL + kt * 64 + lr)) * 64 + lc);
        uint4* dh = (uint4*)(th + lr * 72 + lc);
        uint4* dl = (uint4*)(tl + lr * 72 + lc);
        #pragma unroll
        for (int u = 0; u < 4; u++) { dh[u] = sh[u]; dl[u] = sl[u]; }
    }
    __syncthreads();
    unsigned short* oh = Vthi + ((size_t)(head * 64 + lr)) * SEQL + kt * 64 + lc;
    unsigned short* ol = Vtlo + ((size_t)(head * 64 + lr)) * SEQL + kt * 64 + lc;
    #pragma unroll
    for (int v = 0; v < 4; v++) {
        uint32_t wh[4], wl[4];
        #pragma unroll
        for (int u = 0; u < 4; u++) {
            const int k = lc + v * 8 + u * 2;
            wh[u] = (uint32_t)th[k * 72 + lr] | ((uint32_t)th[(k + 1) * 72 + lr] << 16);
            wl[u] = (uint32_t)tl[k * 72 + lr] | ((uint32_t)tl[(k + 1) * 72 + lr] << 16);
        }
        ((uint4*)oh)[v] = make_uint4(wh[0], wh[1], wh[2], wh[3]);
        ((uint4*)ol)[v] = make_uint4(wl[0], wl[1], wl[2], wl[3]);
    }
}

// ---------------------------------------------------------------------------
// bf16-split GEMM machinery (shared by QKV-fused and QE/Wo kernels)
// Single-sync pipelined mainloop: wait -> sync -> issue(c+1) -> compute(c).
// ---------------------------------------------------------------------------
#define PITCH   40
#define A_HI_O  0
#define A_LO_O  (128 * PITCH)
#define B_HI_O  (2 * 128 * PITCH)
#define B_LO_O  (3 * 128 * PITCH)
#define STAGE_E (4 * 128 * PITCH)
#define SMEM_DYN (2 * STAGE_E * 2)

#define GISSUE(c) do { \
    const uint32_t sb_ = smb + (uint32_t)(((c) & 1) * (STAGE_E * 2)); \
    const size_t ka_ = a_off + (size_t)(c) * 32; \
    const size_t kb_ = b_off + (size_t)(c) * 32; \
    cp16(sb_ + (A_HI_O + s_off) * 2,      Ahi + ka_); \
    cp16(sb_ + (A_HI_O + s_off) * 2 + 16, Ahi + ka_ + 8); \
    cp16(sb_ + (A_LO_O + s_off) * 2,      Alo + ka_); \
    cp16(sb_ + (A_LO_O + s_off) * 2 + 16, Alo + ka_ + 8); \
    cp16(sb_ + (B_HI_O + s_off) * 2,      Bhi + kb_); \
    cp16(sb_ + (B_HI_O + s_off) * 2 + 16, Bhi + kb_ + 8); \
    cp16(sb_ + (B_LO_O + s_off) * 2,      Blo + kb_); \
    cp16(sb_ + (B_LO_O + s_off) * 2 + 16, Blo + kb_ + 8); \
} while (0)

// Mainloop body shared via macro: computes acc[2][8][4] over KT.
#define GEMM_MAINLOOP(KT) do { \
    const int nch = (KT) >> 5; \
    GISSUE(0); \
    cp_commit(); \
    for (int c = 0; c < nch; c++) { \
        cp_wait<0>(); \
        __syncthreads(); \
        if (c + 1 < nch) { GISSUE(c + 1); cp_commit(); } \
        const uint32_t stb = smb + (uint32_t)((c & 1) * (STAGE_E * 2)); \
        _Pragma("unroll") \
        for (int kk = 0; kk < 32; kk += 16) { \
            uint32_t ah[2][4], al[2][4]; \
            _Pragma("unroll") \
            for (int mt = 0; mt < 2; mt++) { \
                const uint32_t aoff = \
                    (uint32_t)((warp_m * 32 + mt * 16 + lrow16) * PITCH + kk + lcol8) * 2; \
                ldsm4(stb + A_HI_O * 2 + aoff, ah[mt][0], ah[mt][1], ah[mt][2], ah[mt][3]); \
                ldsm4(stb + A_LO_O * 2 + aoff, al[mt][0], al[mt][1], al[mt][2], al[mt][3]); \
            } \
            uint32_t bh[8][2], bl[8][2]; \
            _Pragma("unroll") \
            for (int grp = 0; grp < 4; grp++) { \
                const uint32_t boff = \
                    (uint32_t)((warp_n * 64 + grp * 16 + lrow16) * PITCH + kk + lcol8) * 2; \
                uint32_t r0, r1, r2, r3; \
                ldsm4(stb + B_HI_O * 2 + boff, r0, r1, r2, r3); \
                bh[grp * 2][0] = r0; bh[grp * 2][1] = r2; \
                bh[grp * 2 + 1][0] = r1; bh[grp * 2 + 1][1] = r3; \
                ldsm4(stb + B_LO_O * 2 + boff, r0, r1, r2, r3); \
                bl[grp * 2][0] = r0; bl[grp * 2][1] = r2; \
                bl[grp * 2 + 1][0] = r1; bl[grp * 2 + 1][1] = r3; \
            } \
            _Pragma("unroll") \
            for (int mt = 0; mt < 2; mt++) \
                _Pragma("unroll") \
                for (int nt = 0; nt < 8; nt++) { \
                    MMA_BF16(acc[mt][nt], ah[mt], bh[nt]); \
                    MMA_BF16(acc[mt][nt], ah[mt], bl[nt]); \
                    MMA_BF16(acc[mt][nt], al[mt], bh[nt]); \
                } \
        } \
    } \
} while (0)

// QKV projections fused over blockIdx.z; writes bf16 hi/lo head layout.
__global__ __launch_bounds__(256) void ra_mma_gemm_qkv(
    const unsigned short* __restrict__ XhB, const unsigned short* __restrict__ XlB,
    const unsigned short* __restrict__ BhB, const unsigned short* __restrict__ BlB,
    const float* __restrict__ bq, const float* __restrict__ bk,
    const float* __restrict__ bv,
    unsigned short* __restrict__ Qh, unsigned short* __restrict__ Ql,
    unsigned short* __restrict__ Kh, unsigned short* __restrict__ Kl,
    unsigned short* __restrict__ Vh, unsigned short* __restrict__ Vl)
{
    const int z = blockIdx.z;
    const unsigned short* Ahi = XhB + (size_t)z * (NLROWS * DMODEL);
    const unsigned short* Alo = XlB + (size_t)z * (NLROWS * DMODEL);
    const unsigned short* Bhi = BhB + (size_t)z * (DMODEL * DMODEL);
    const unsigned short* Blo = BlB + (size_t)z * (DMODEL * DMODEL);
    const float* bias = z == 0 ? bq : (z == 1 ? bk : bv);
    unsigned short* outh = z == 0 ? Qh : (z == 1 ? Kh : Vh);
    unsigned short* outl = z == 0 ? Ql : (z == 1 ? Kl : Vl);
    const float scale = (z == 0) ? 0.125f : 1.0f;

    const int m0 = blockIdx.y * 128;
    const int n0 = blockIdx.x * 128;
    extern __shared__ unsigned short sm[];
    const uint32_t smb = smem_u32(sm);

    const int tid    = threadIdx.x;
    const int wid    = tid >> 5;
    const int lane   = tid & 31;
    const int warp_m = wid & 3;
    const int warp_n = wid >> 2;
    const int lrow16 = lane & 15;
    const int lcol8  = (lane >> 4) << 3;

    const int glr = tid >> 1;
    const int glc = (tid & 1) * 16;
    const size_t a_off = (size_t)(m0 + glr) * DMODEL + glc;
    const size_t b_off = (size_t)(n0 + glr) * DMODEL + glc;
    const int    s_off = glr * PITCH + glc;

    float acc[2][8][4];
    #pragma unroll
    for (int mt = 0; mt < 2; mt++)
        #pragma unroll
        for (int nt = 0; nt < 8; nt++)
            #pragma unroll
            for (int i = 0; i < 4; i++) acc[mt][nt][i] = 0.f;

    GEMM_MAINLOOP(DMODEL);

    // Epilogue: bf16 hi/lo head layout
    const int rbase = m0 + warp_m * 32 + (lane >> 2);
    const int cbase = n0 + warp_n * 64 + (lane & 3) * 2;
    #pragma unroll
    for (int mt = 0; mt < 2; mt++) {
        #pragma unroll
        for (int nt = 0; nt < 8; nt++) {
            const int col = cbase + nt * 8;
            const float b0 = bias[col], b1 = bias[col + 1];
            #pragma unroll
            for (int half = 0; half < 2; half++) {
                const int row = rbase + mt * 16 + half * 8;
                const float v0 = (acc[mt][nt][half * 2 + 0] + b0) * scale;
                const float v1 = (acc[mt][nt][half * 2 + 1] + b1) * scale;
                const int n = row >> 10, l = row & (SEQL - 1);
                const int h = (col >> 6) & (NHEADS - 1);
                const size_t oidx =
                    ((size_t)((n * NHEADS + h) * SEQL + l)) * DEPTH + (col & 63);
                const uint32_t hp = packbf(v0, v1);
                *(uint32_t*)(outh + oidx) = hp;
                *(uint32_t*)(outl + oidx) =
                    packbf(v0 - __uint_as_float(hp << 16),
                           v1 - __uint_as_float(hp & 0xffff0000u));
            }
        }
    }
}

// QE band (omode 2, bf16 out) / Wo projection (omode 0, f32 out)
__global__ __launch_bounds__(256) void ra_mma_gemm(
    const unsigned short* __restrict__ Ahi, const unsigned short* __restrict__ Alo,
    const unsigned short* __restrict__ Bhi, const unsigned short* __restrict__ Blo,
    const float* __restrict__ bias, float* __restrict__ outf, int KT, int omode)
{
    const int m0 = blockIdx.y * 128;
    const int n0 = blockIdx.x * 128;
    if (omode == 2) {
        const int i0 = m0 & (SEQL - 1);
        if (n0 + 127 < (SEQL - 128) - i0) return;   // band never read
    }
    extern __shared__ unsigned short sm[];
    const uint32_t smb = smem_u32(sm);

    const int tid    = threadIdx.x;
    const int wid    = tid >> 5;
    const int lane   = tid & 31;
    const int warp_m = wid & 3;
    const int warp_n = wid >> 2;
    const int lrow16 = lane & 15;
    const int lcol8  = (lane >> 4) << 3;

    const int glr = tid >> 1;
    const int glc = (tid & 1) * 16;
    const size_t a_off = (size_t)(m0 + glr) * KT + glc;
    const size_t b_off = (size_t)(n0 + glr) * KT + glc;
    const int    s_off = glr * PITCH + glc;

    float acc[2][8][4];
    #pragma unroll
    for (int mt = 0; mt < 2; mt++)
        #pragma unroll
        for (int nt = 0; nt < 8; nt++)
            #pragma unroll
            for (int i = 0; i < 4; i++) acc[mt][nt][i] = 0.f;

    GEMM_MAINLOOP(KT);

    const int rbase = m0 + warp_m * 32 + (lane >> 2);
    const int cbase = n0 + warp_n * 64 + (lane & 3) * 2;
    unsigned short* ob16 = (unsigned short*)outf;   // omode 2: bf16 band
    #pragma unroll
    for (int mt = 0; mt < 2; mt++) {
        #pragma unroll
        for (int nt = 0; nt < 8; nt++) {
            const int col = cbase + nt * 8;
            const float b0 = bias[col], b1 = bias[col + 1];
            #pragma unroll
            for (int half = 0; half < 2; half++) {
                const int row = rbase + mt * 16 + half * 8;
                const float v0 = acc[mt][nt][half * 2 + 0] + b0;
                const float v1 = acc[mt][nt][half * 2 + 1] + b1;
                if (omode == 0) {
                    *(float2*)(outf + (size_t)row * DMODEL + col) = make_float2(v0, v1);
                } else {
                    const int i = row & (SEQL - 1);
                    const int j = col + i - (SEQL - 1);
                    if (j >= 0)
                        ob16[(size_t)row * SEQL + j] =
                            __bfloat16_as_ushort(__float2bfloat16(v0));
                    if (j + 1 >= 0)
                        ob16[(size_t)row * SEQL + j + 1] =
                            __bfloat16_as_ushort(__float2bfloat16(v1));
                }
            }
        }
    }
}

// ---------------------------------------------------------------------------
// MMA flash attention: 128-query tiles, 256 threads, single-sync pipeline,
// dead-warp skip on the final (fully masked) j-tile.
// ---------------------------------------------------------------------------
#define AT_KHI     0
#define AT_KLO     9216
#define AT_VHI     18432
#define AT_VLO     27648
#define AT_BIAS    36864
#define AT_STAGE_B 55296               // 36864 + 128*72*2
#define AT_SMEM    (2 * AT_STAGE_B)    // 110592 bytes

__device__ __forceinline__ void attn_issue(
    uint32_t sb, int nh, int i0, int j0, int tid,
    const unsigned short* __restrict__ Khi, const unsigned short* __restrict__ Klo,
    const unsigned short* __restrict__ Vthi, const unsigned short* __restrict__ Vtlo,
    const unsigned short* __restrict__ QE)
{
    // K/V: 64 rows x 64 u16 each; thread t -> row t>>2, 16-elem quarter (t&3)
    const int kr = tid >> 2, kc = (tid & 3) * 16;
    const size_t krow = ((size_t)(nh * SEQL + j0 + kr)) * 64 + kc;
    const size_t vrow = ((size_t)(nh * 64 + kr)) * SEQL + j0 + kc;
    const uint32_t so = (uint32_t)(kr * 72 + kc) * 2;
    #pragma unroll
    for (int u = 0; u < 2; u++) {
        cp16(sb + AT_KHI + so + u * 16, Khi + krow + u * 8);
        cp16(sb + AT_KLO + so + u * 16, Klo + krow + u * 8);
        cp16(sb + AT_VHI + so + u * 16, Vthi + vrow + u * 8);
        cp16(sb + AT_VLO + so + u * 16, Vtlo + vrow + u * 8);
    }
    // bias: 128 rows x 64 bf16; thread t -> row t>>1, 32-elem half (t&1)
    const int br = tid >> 1, bc = (tid & 1) * 32;
    const unsigned short* gb = QE + (size_t)(nh * SEQL + i0 + br) * SEQL + j0 + bc;
    const uint32_t sbia = sb + AT_BIAS + (uint32_t)(br * 72 + bc) * 2;
    #pragma unroll
    for (int u = 0; u < 4; u++)
        cp16(sbia + u * 16, gb + u * 8);
}

__global__ __launch_bounds__(256, 2) void ra_attn_mma(
    const unsigned short* __restrict__ Qhi, const unsigned short* __restrict__ Qlo,
    const unsigned short* __restrict__ Khi, const unsigned short* __restrict__ Klo,
    const unsigned short* __restrict__ Vthi, const unsigned short* __restrict__ Vtlo,
    const unsigned short* __restrict__ QE,
    unsigned short* __restrict__ AOhi, unsigned short* __restrict__ AOlo)
{
    extern __shared__ char smc[];
    const uint32_t smb = smem_u32(smc);
    const int nh = blockIdx.y;
    const int i0 = (int)(gridDim.x - 1 - blockIdx.x) * 128;   // big tiles first
    const int t = threadIdx.x;
    const int w = t >> 5, lane = t & 31;
    const int g = lane >> 2, q4 = lane & 3;
    const int lrow16 = lane & 15, lcol8 = (lane >> 4) << 3;
    const int ntj = (i0 >> 6) + 1;    // last j-tile index (diagonal spans 2 tiles)

    attn_issue(smb, nh, i0, 0, t, Khi, Klo, Vthi, Vtlo, QE);
    cp_commit();

    // ---- Q fragments via staging in stage-1 region (free until issue(1)) ----
    const int qr = t >> 1, qc = (t & 1) * 32;   // 128 rows x 64 u16
    uint32_t qh[4][4], ql[4][4];
    {
        const uint4* src = (const uint4*)(Qhi + ((size_t)(nh * SEQL + i0 + qr)) * 64 + qc);
        uint4* dst = (uint4*)(smc + AT_STAGE_B + (qr * 72 + qc) * 2);
        #pragma unroll
        for (int u = 0; u < 4; u++) dst[u] = src[u];
    }
    __syncthreads();
    #pragma unroll
    for (int kt = 0; kt < 4; kt++)
        ldsm4(smb + AT_STAGE_B + (uint32_t)((16 * w + lrow16) * 72 + kt * 16 + lcol8) * 2,
              qh[kt][0], qh[kt][1], qh[kt][2], qh[kt][3]);
    __syncthreads();
    {
        const uint4* src = (const uint4*)(Qlo + ((size_t)(nh * SEQL + i0 + qr)) * 64 + qc);
        uint4* dst = (uint4*)(smc + AT_STAGE_B + (qr * 72 + qc) * 2);
        #pragma unroll
        for (int u = 0; u < 4; u++) dst[u] = src[u];
    }
    __syncthreads();
    #pragma unroll
    for (int kt = 0; kt < 4; kt++)
        ldsm4(smb + AT_STAGE_B + (uint32_t)((16 * w + lrow16) * 72 + kt * 16 + lcol8) * 2,
              ql[kt][0], ql[kt][1], ql[kt][2], ql[kt][3]);

    float o[8][4];
    #pragma unroll
    for (int nt = 0; nt < 8; nt++)
        #pragma unroll
        for (int i = 0; i < 4; i++) o[nt][i] = 0.f;
    float rm[2] = {-1e30f, -1e30f};
    float rl[2] = {0.f, 0.f};

    for (int c = 0; c <= ntj; c++) {
        cp_wait<0>();
        __syncthreads();   // stage c ready AND all reads of stage (c-1)&1 done
        if (c < ntj) {
            attn_issue(smb + (uint32_t)(((c + 1) & 1) * AT_STAGE_B),
                       nh, i0, (c + 1) * 64, t, Khi, Klo, Vthi, Vtlo, QE);
            cp_commit();
        }

        // Final tile: rows of warps 0-3 (i0..i0+63) are fully masked -> skip.
        if (c == ntj && w < 4) continue;

        const uint32_t stg = smb + (uint32_t)((c & 1) * AT_STAGE_B);
        const char* stgc = smc + (size_t)((c & 1) * AT_STAGE_B);
        const int j0 = c * 64;

        // ---- S = QK^T (3-term split) ----
        float s[8][4];
        #pragma unroll
        for (int nt = 0; nt < 8; nt++)
            #pragma unroll
            for (int i = 0; i < 4; i++) s[nt][i] = 0.f;
        #pragma unroll
        for (int kt = 0; kt < 4; kt++) {
            uint32_t kbh[8][2], kbl[8][2];
            #pragma unroll
            for (int grp = 0; grp < 4; grp++) {
                const uint32_t off = (uint32_t)((grp * 16 + lrow16) * 72 + kt * 16 + lcol8) * 2;
                uint32_t r0, r1, r2, r3;
                ldsm4(stg + AT_KHI + off, r0, r1, r2, r3);
                kbh[grp * 2][0] = r0; kbh[grp * 2][1] = r2;
                kbh[grp * 2 + 1][0] = r1; kbh[grp * 2 + 1][1] = r3;
                ldsm4(stg + AT_KLO + off, r0, r1, r2, r3);
                kbl[grp * 2][0] = r0; kbl[grp * 2][1] = r2;
                kbl[grp * 2 + 1][0] = r1; kbl[grp * 2 + 1][1] = r3;
            }
            #pragma unroll
            for (int nt = 0; nt < 8; nt++) {
                MMA_BF16(s[nt], qh[kt], kbh[nt]);
                MMA_BF16(s[nt], qh[kt], kbl[nt]);
                MMA_BF16(s[nt], ql[kt], kbh[nt]);
            }
        }

        // ---- bias + causal mask ----
        const int r0l = 16 * w + g, r1l = r0l + 8;
        #pragma unroll
        for (int nt = 0; nt < 8; nt++) {
            const int cl = nt * 8 + q4 * 2;
            const uint32_t b0 = *(const uint32_t*)(stgc + AT_BIAS + (r0l * 72 + cl) * 2);
            const uint32_t b1 = *(const uint32_t*)(stgc + AT_BIAS + (r1l * 72 + cl) * 2);
            s[nt][0] += __uint_as_float(b0 << 16);
            s[nt][1] += __uint_as_float(b0 & 0xffff0000u);
            s[nt][2] += __uint_as_float(b1 << 16);
            s[nt][3] += __uint_as_float(b1 & 0xffff0000u);
        }
        if (c >= ntj - 1) {
            const int ig0 = i0 + r0l, ig1 = i0 + r1l;
            #pragma unroll
            for (int nt = 0; nt < 8; nt++) {
                const int jg = j0 + nt * 8 + q4 * 2;
                if (jg     > ig0) s[nt][0] = -1e30f;
                if (jg + 1 > ig0) s[nt][1] = -1e30f;
                if (jg     > ig1) s[nt][2] = -1e30f;
                if (jg + 1 > ig1) s[nt][3] = -1e30f;
            }
        }

        // ---- online softmax ----
        float mx0 = -1e30f, mx1 = -1e30f;
        #pragma unroll
        for (int nt = 0; nt < 8; nt++) {
            mx0 = fmaxf(mx0, fmaxf(s[nt][0], s[nt][1]));
            mx1 = fmaxf(mx1, fmaxf(s[nt][2], s[nt][3]));
        }
        mx0 = fmaxf(mx0, __shfl_xor_sync(0xffffffffu, mx0, 1));
        mx0 = fmaxf(mx0, __shfl_xor_sync(0xffffffffu, mx0, 2));
        mx1 = fmaxf(mx1, __shfl_xor_sync(0xffffffffu, mx1, 1));
        mx1 = fmaxf(mx1, __shfl_xor_sync(0xffffffffu, mx1, 2));
        const float m0n = fmaxf(rm[0], mx0);
        const float m1n = fmaxf(rm[1], mx1);
        const float a0 = __expf(rm[0] - m0n);
        const float a1 = __expf(rm[1] - m1n);
        float ps0 = 0.f, ps1 = 0.f;
        uint32_t ph[4][4], pl[4][4];
        #pragma unroll
        for (int nt = 0; nt < 8; nt++) {
            const float p0 = __expf(s[nt][0] - m0n);
            const float p1 = __expf(s[nt][1] - m0n);
            const float p2 = __expf(s[nt][2] - m1n);
            const float p3 = __expf(s[nt][3] - m1n);
            ps0 += p0 + p1; ps1 += p2 + p3;
            const int kt = nt >> 1, sl = (nt & 1) * 2;
            const uint32_t hp01 = packbf(p0, p1);
            const uint32_t hp23 = packbf(p2, p3);
            ph[kt][sl + 0] = hp01;
            ph[kt][sl + 1] = hp23;
            pl[kt][sl + 0] = packbf(p0 - __uint_as_float(hp01 << 16),
                                    p1 - __uint_as_float(hp01 & 0xffff0000u));
            pl[kt][sl + 1] = packbf(p2 - __uint_as_float(hp23 << 16),
                                    p3 - __uint_as_float(hp23 & 0xffff0000u));
        }
        ps0 += __shfl_xor_sync(0xffffffffu, ps0, 1);
        ps0 += __shfl_xor_sync(0xffffffffu, ps0, 2);
        ps1 += __shfl_xor_sync(0xffffffffu, ps1, 1);
        ps1 += __shfl_xor_sync(0xffffffffu, ps1, 2);
        rl[0] = rl[0] * a0 + ps0;
        rl[1] = rl[1] * a1 + ps1;
        rm[0] = m0n; rm[1] = m1n;
        #pragma unroll
        for (int nt = 0; nt < 8; nt++) {
            o[nt][0] *= a0; o[nt][1] *= a0;
            o[nt][2] *= a1; o[nt][3] *= a1;
        }

        // ---- O += P @ V (3-term split) ----
        #pragma unroll
        for (int kt = 0; kt < 4; kt++) {
            uint32_t vbh[8][2], vbl[8][2];
            #pragma unroll
            for (int grp = 0; grp < 4; grp++) {
                const uint32_t off = (uint32_t)((grp * 16 + lrow16) * 72 + kt * 16 + lcol8) * 2;
                uint32_t r0, r1, r2, r3;
                ldsm4(stg + AT_VHI + off, r0, r1, r2, r3);
                vbh[grp * 2][0] = r0; vbh[grp * 2][1] = r2;
                vbh[grp * 2 + 1][0] = r1; vbh[grp * 2 + 1][1] = r3;
                ldsm4(stg + AT_VLO + off, r0, r1, r2, r3);
                vbl[grp * 2][0] = r0; vbl[grp * 2][1] = r2;
                vbl[grp * 2 + 1][0] = r1; vbl[grp * 2 + 1][1] = r3;
            }
            #pragma unroll
            for (int nt = 0; nt < 8; nt++) {
                MMA_BF16(o[nt], ph[kt], vbh[nt]);
                MMA_BF16(o[nt], ph[kt], vbl[nt]);
                MMA_BF16(o[nt], pl[kt], vbh[nt]);
            }
        }
    }

    // ---- epilogue: normalize, split, write AO hi/lo (natural layout) ----
    const float inv0 = 1.f / rl[0], inv1 = 1.f / rl[1];
    const int n = nh >> 4, h = nh & (NHEADS - 1);
    const int r0g = i0 + 16 * w + g, r1g = r0g + 8;
    #pragma unroll
    for (int nt = 0; nt < 8; nt++) {
        const int col = h * 64 + nt * 8 + q4 * 2;
        const float v0 = o[nt][0] * inv0, v1 = o[nt][1] * inv0;
        const float v2 = o[nt][2] * inv1, v3 = o[nt][3] * inv1;
        const size_t idx0 = ((size_t)(n * SEQL + r0g)) * DMODEL + col;
        const size_t idx1 = ((size_t)(n * SEQL + r1g)) * DMODEL + col;
        const uint32_t hp01 = packbf(v0, v1);
        const uint32_t hp23 = packbf(v2, v3);
        *(uint32_t*)(AOhi + idx0) = hp01;
        *(uint32_t*)(AOhi + idx1) = hp23;
        *(uint32_t*)(AOlo + idx0) = packbf(v0 - __uint_as_float(hp01 << 16),
                                           v1 - __uint_as_float(hp01 & 0xffff0000u));
        *(uint32_t*)(AOlo + idx1) = packbf(v2 - __uint_as_float(hp23 << 16),
                                           v3 - __uint_as_float(hp23 & 0xffff0000u));
    }
}

// ---------------------------------------------------------------------------
extern "C" void kernel_launch(void* const* d_in, const int* in_sizes, int n_in,
                              void* d_out, int out_size)
{
    (void)in_sizes; (void)n_in; (void)out_size;
    const float* q_in    = (const float*)d_in[0];
    const float* k_in    = (const float*)d_in[1];
    const float* v_in    = (const float*)d_in[2];
    /* d_in[3] = mask (triu k=1) — handled analytically */
    const float* Wq      = (const float*)d_in[4];
    const float* bq      = (const float*)d_in[5];
    const float* Wk      = (const float*)d_in[6];
    const float* bk      = (const float*)d_in[7];
    const float* Wv      = (const float*)d_in[8];
    const float* bv      = (const float*)d_in[9];
    const float* Wo      = (const float*)d_in[10];
    const float* bo      = (const float*)d_in[11];
    const float* pos_emb = (const float*)d_in[12];

    unsigned short* QEp;
    float* zb;
    unsigned short (*Xh)[NLROWS * DMODEL], (*Xl)[NLROWS * DMODEL];
    unsigned short (*Bh)[DMODEL * DMODEL], (*Bl)[DMODEL * DMODEL];
    unsigned short *Eh, *El, *Qh, *Ql, *Kh, *Kl, *Vh, *Vl, *Vth, *Vtl;
    cudaGetSymbolAddress((void**)&QEp, g_QE);
    cudaGetSymbolAddress((void**)&zb,  g_zbias);
    cudaGetSymbolAddress((void**)&Xh,  g_Xhi);
    cudaGetSymbolAddress((void**)&Xl,  g_Xlo);
    cudaGetSymbolAddress((void**)&Bh,  g_Bhi);
    cudaGetSymbolAddress((void**)&Bl,  g_Blo);
    cudaGetSymbolAddress((void**)&Eh,  g_Ehi);
    cudaGetSymbolAddress((void**)&El,  g_Elo);
    cudaGetSymbolAddress((void**)&Qh,  g_Qhi);
    cudaGetSymbolAddress((void**)&Ql,  g_Qlo);
    cudaGetSymbolAddress((void**)&Kh,  g_Khi);
    cudaGetSymbolAddress((void**)&Kl,  g_Klo);
    cudaGetSymbolAddress((void**)&Vh,  g_Vhi);
    cudaGetSymbolAddress((void**)&Vl,  g_Vlo);
    cudaGetSymbolAddress((void**)&Vth, g_Vthi);
    cudaGetSymbolAddress((void**)&Vtl, g_Vtlo);

    cudaFuncSetAttribute(ra_mma_gemm, cudaFuncAttributeMaxDynamicSharedMemorySize,
                         SMEM_DYN);
    cudaFuncSetAttribute(ra_mma_gemm_qkv, cudaFuncAttributeMaxDynamicSharedMemorySize,
                         SMEM_DYN);
    cudaFuncSetAttribute(ra_attn_mma, cudaFuncAttributeMaxDynamicSharedMemorySize,
                         AT_SMEM);

    const int n4x = (NLROWS * DMODEL) / 4;

    // All conversions up front (fused launches)
    ra_conv_hilo3<<<dim3(n4x / 256, 3), 256>>>(q_in, k_in, v_in,
                                               Xh[0], Xl[0], Xh[1], Xl[1],
                                               Xh[2], Xl[2], n4x);
    ra_conv_wt4<<<dim3(32, 32, 4), dim3(32, 8)>>>(Wq, Wk, Wv, Wo,
                                                  Bh[0], Bl[0], Bh[1], Bl[1],
                                                  Bh[2], Bl[2], Bh[3], Bl[3]);
    ra_conv_hilo<<<(SEQL * DEPTH / 4) / 256, 256>>>(pos_emb + SEQL * DEPTH,
                                                    Eh, El, SEQL * DEPTH / 4);

    // Q/K/V projections fused into one launch (Q carries 1/sqrt(d))
    ra_mma_gemm_qkv<<<dim3(DMODEL / 128, NLROWS / 128, 3), 256, SMEM_DYN>>>(
        Xh[0], Xl[0], Bh[0], Bl[0], bq, bk, bv, Qh, Ql, Kh, Kl, Vh, Vl);
    ra_vt<<<dim3(16, NHTOT), 128>>>(Vh, Vl, Vth, Vtl);

    // QE = Q @ E^T (K=64), diag-shifted band, bf16 output
    ra_mma_gemm<<<dim3(SEQL / 128, QROWS / 128), 256, SMEM_DYN>>>(
        Qh, Ql, Eh, El, zb, (float*)QEp, DEPTH, 2);

    // Pipelined MMA flash attention, 128-query tiles -> AO hi/lo (reuses X[0])
    ra_attn_mma<<<dim3(SEQL / 128, NHTOT), 256, AT_SMEM>>>(
        Qh, Ql, Kh, Kl, Vth, Vtl, QEp, Xh[0], Xl[0]);

    // Output projection -> f32 d_out
    ra_mma_gemm<<<dim3(DMODEL / 128, NLROWS / 128), 256, SMEM_DYN>>>(
        Xh[0], Xl[0], Bh[3], Bl[3], bo, (float*)d_out, DMODEL, 0);
}